// round 3
// baseline (speedup 1.0000x reference)
#include <cuda_runtime.h>
#include <cuda_bf16.h>
#include <math.h>

// ---------------------------------------------------------------------------
// ChannelCrossAttention  (XCA, cross-stream):
//   qkv = x @ Wqkv  -> (q,k,v) in (B,H,d,N) layout, d=64, N=4096
//   logits = (q@k^T)/(|q||k|) * temp  (64x64 per (b,h)), softmax, out = P@v
//   y = out @ Wproj + b
// Streams cross: out_rgb uses q_rgb with k_T,v_T;  out_T uses q_T with k_rgb,v_rgb.
// ---------------------------------------------------------------------------

#define BDIM   8
#define NTOK   4096
#define CDIM   512
#define HEADS  8
#define DH     64

// scratch: qkv[s][w][b][h*64+d][n]   s=stream, w=q/k/v
__device__ float g_qkv[2u * 3u * 8u * 512u * 4096u];   // 402 MB
// attention output, [s][b][k=h*64+d][n]
__device__ float g_att[2u * 8u * 512u * 4096u];        // 134 MB

// ---------------------------------------------------------------------------
// Kernel 1: qkv = X @ W (K=512 -> 1536), scatter to (B,H,d,N) layout.
// Output tile: rows = output channel c (128), cols = token m (128).
// ---------------------------------------------------------------------------
__global__ __launch_bounds__(256) void qkv_gemm_kernel(
    const float* __restrict__ x, const float* __restrict__ x_d,
    const float* __restrict__ Wr, const float* __restrict__ Wt)
{
    const int s  = blockIdx.z;
    const float* __restrict__ X = s ? x_d : x;
    const float* __restrict__ W = s ? Wt  : Wr;

    const int m0 = blockIdx.x * 128;     // token index (b*4096+n)
    const int c0 = blockIdx.y * 128;     // output channel
    const int b  = m0 >> 12;
    const int n0 = m0 & 4095;

    __shared__ float Ws[16][128];
    __shared__ float Xs[16][128];

    const int tid = threadIdx.x;
    const int ty = tid >> 4;    // c-group
    const int tx = tid & 15;    // m-group

    float acc[8][8];
#pragma unroll
    for (int i = 0; i < 8; i++)
#pragma unroll
        for (int j = 0; j < 8; j++) acc[i][j] = 0.f;

    for (int k0 = 0; k0 < 512; k0 += 16) {
#pragma unroll
        for (int it = 0; it < 2; it++) {
            int idx = tid + it * 256;          // 0..511
            int kk = idx >> 5;
            int cq = idx & 31;
            float4 w4 = *(const float4*)&W[(size_t)(k0 + kk) * 1536 + c0 + cq * 4];
            *(float4*)&Ws[kk][cq * 4] = w4;
        }
#pragma unroll
        for (int it = 0; it < 2; it++) {
            int idx = tid + it * 256;
            int mm = idx >> 2;
            int kq = idx & 3;
            float4 x4 = *(const float4*)&X[(size_t)(m0 + mm) * 512 + k0 + kq * 4];
            Xs[kq * 4 + 0][mm] = x4.x;
            Xs[kq * 4 + 1][mm] = x4.y;
            Xs[kq * 4 + 2][mm] = x4.z;
            Xs[kq * 4 + 3][mm] = x4.w;
        }
        __syncthreads();
#pragma unroll
        for (int kk = 0; kk < 16; kk++) {
            float rc[8], rm[8];
#pragma unroll
            for (int i = 0; i < 8; i++) rc[i] = Ws[kk][ty * 8 + i];
#pragma unroll
            for (int j = 0; j < 8; j++) rm[j] = Xs[kk][tx * 8 + j];
#pragma unroll
            for (int i = 0; i < 8; i++)
#pragma unroll
                for (int j = 0; j < 8; j++) acc[i][j] += rc[i] * rm[j];
        }
        __syncthreads();
    }

    // epilogue: scatter into g_qkv[(s*3+which)][b][rem][n]
#pragma unroll
    for (int i = 0; i < 8; i++) {
        int c = c0 + ty * 8 + i;
        int which = c >> 9;           // 0=q 1=k 2=v
        int rem = c & 511;            // h*64+d
        size_t base = ((size_t)((s * 3 + which) * 8 + b)) * 2097152
                    + (size_t)rem * 4096 + n0 + tx * 8;
        float4 v0 = make_float4(acc[i][0], acc[i][1], acc[i][2], acc[i][3]);
        float4 v1 = make_float4(acc[i][4], acc[i][5], acc[i][6], acc[i][7]);
        *(float4*)&g_qkv[base]     = v0;
        *(float4*)&g_qkv[base + 4] = v1;
    }
}

// ---------------------------------------------------------------------------
// Kernel 2: per (s, b, h): Gram + norms + softmax + P@V.
//   s=0 -> out_rgb: q from stream0, k/v from stream1, temp_rgb
//   s=1 -> out_T  : q from stream1, k/v from stream0, temp_T
// ---------------------------------------------------------------------------
__global__ __launch_bounds__(256) void attn_kernel(
    const float* __restrict__ temp_rgb, const float* __restrict__ temp_T)
{
    const int s  = blockIdx.y;
    const int bh = blockIdx.x;
    const int b = bh >> 3;
    const int h = bh & 7;
    const int so = s ^ 1;

    const float* __restrict__ q = g_qkv + ((size_t)((s  * 3 + 0) * 8 + b)) * 2097152 + (size_t)h * 64 * 4096;
    const float* __restrict__ k = g_qkv + ((size_t)((so * 3 + 1) * 8 + b)) * 2097152 + (size_t)h * 64 * 4096;
    const float* __restrict__ v = g_qkv + ((size_t)((so * 3 + 2) * 8 + b)) * 2097152 + (size_t)h * 64 * 4096;
    const float temp = (s ? temp_T : temp_rgb)[h];

    __shared__ float bufA[64 * 65];
    __shared__ float bufB[64 * 65];
    __shared__ float qn[64], kn[64];

    const int tid = threadIdx.x;
    const int ty = tid >> 4;
    const int tx = tid & 15;

    float acc[4][4];
#pragma unroll
    for (int i = 0; i < 4; i++)
#pragma unroll
        for (int j = 0; j < 4; j++) acc[i][j] = 0.f;
    float nacc = 0.f;

    // -------- pass 1: G = q @ k^T over N, plus sum-of-squares per row ------
    for (int ch = 0; ch < 64; ch++) {
        const int nn0 = ch * 64;
#pragma unroll
        for (int it = 0; it < 4; it++) {
            int idx = tid + it * 256;       // 0..1023
            int r  = idx >> 4;
            int nq = idx & 15;
            float4 a4 = *(const float4*)&q[(size_t)r * 4096 + nn0 + nq * 4];
            bufA[r * 65 + nq * 4 + 0] = a4.x;
            bufA[r * 65 + nq * 4 + 1] = a4.y;
            bufA[r * 65 + nq * 4 + 2] = a4.z;
            bufA[r * 65 + nq * 4 + 3] = a4.w;
            float4 b4 = *(const float4*)&k[(size_t)r * 4096 + nn0 + nq * 4];
            bufB[r * 65 + nq * 4 + 0] = b4.x;
            bufB[r * 65 + nq * 4 + 1] = b4.y;
            bufB[r * 65 + nq * 4 + 2] = b4.z;
            bufB[r * 65 + nq * 4 + 3] = b4.w;
        }
        __syncthreads();
#pragma unroll 8
        for (int nn = 0; nn < 64; nn++) {
            float rq[4], rk[4];
#pragma unroll
            for (int i = 0; i < 4; i++) rq[i] = bufA[(ty * 4 + i) * 65 + nn];
#pragma unroll
            for (int j = 0; j < 4; j++) rk[j] = bufB[(tx * 4 + j) * 65 + nn];
#pragma unroll
            for (int i = 0; i < 4; i++)
#pragma unroll
                for (int j = 0; j < 4; j++) acc[i][j] += rq[i] * rk[j];
        }
        if (tid < 64) {
            float s2 = 0.f;
#pragma unroll 8
            for (int nn = 0; nn < 64; nn++) { float a = bufA[tid * 65 + nn]; s2 += a * a; }
            nacc += s2;
        } else if (tid < 128) {
            int r = tid - 64;
            float s2 = 0.f;
#pragma unroll 8
            for (int nn = 0; nn < 64; nn++) { float a = bufB[r * 65 + nn]; s2 += a * a; }
            nacc += s2;
        }
        __syncthreads();
    }

    if (tid < 64)       qn[tid]      = sqrtf(nacc);
    else if (tid < 128) kn[tid - 64] = sqrtf(nacc);
    // write Gram into bufB (ks no longer needed)
#pragma unroll
    for (int i = 0; i < 4; i++)
#pragma unroll
        for (int j = 0; j < 4; j++)
            bufB[(ty * 4 + i) * 65 + tx * 4 + j] = acc[i][j];
    __syncthreads();

    // -------- softmax over 64 cols, with norm + temperature fold ----------
    if (tid < 64) {
        const int i = tid;
        const float qi = fmaxf(qn[i], 1e-12f);
        float mx = -1e30f;
        for (int j = 0; j < 64; j++) {
            float val = bufB[i * 65 + j] * temp / (qi * fmaxf(kn[j], 1e-12f));
            bufB[i * 65 + j] = val;
            mx = fmaxf(mx, val);
        }
        float sum = 0.f;
        for (int j = 0; j < 64; j++) {
            float e = __expf(bufB[i * 65 + j] - mx);
            bufB[i * 65 + j] = e;
            sum += e;
        }
        float inv = 1.f / sum;
        for (int j = 0; j < 64; j++) bufB[i * 65 + j] *= inv;
    }
    __syncthreads();

    // -------- pass 2: out = P @ v, streamed over N -------------------------
    const size_t attbase = ((size_t)(s * 8 + b)) * 2097152;
    for (int ch = 0; ch < 64; ch++) {
        const int nn0 = ch * 64;
#pragma unroll
        for (int it = 0; it < 4; it++) {
            int idx = tid + it * 256;
            int r  = idx >> 4;
            int nq = idx & 15;
            float4 a4 = *(const float4*)&v[(size_t)r * 4096 + nn0 + nq * 4];
            bufA[r * 65 + nq * 4 + 0] = a4.x;
            bufA[r * 65 + nq * 4 + 1] = a4.y;
            bufA[r * 65 + nq * 4 + 2] = a4.z;
            bufA[r * 65 + nq * 4 + 3] = a4.w;
        }
        __syncthreads();
        float o[4][4];
#pragma unroll
        for (int i = 0; i < 4; i++)
#pragma unroll
            for (int j = 0; j < 4; j++) o[i][j] = 0.f;
#pragma unroll 8
        for (int j = 0; j < 64; j++) {
            float p[4], vv[4];
#pragma unroll
            for (int ii = 0; ii < 4; ii++) p[ii] = bufB[(ty * 4 + ii) * 65 + j];
#pragma unroll
            for (int jj = 0; jj < 4; jj++) vv[jj] = bufA[j * 65 + tx * 4 + jj];
#pragma unroll
            for (int ii = 0; ii < 4; ii++)
#pragma unroll
                for (int jj = 0; jj < 4; jj++) o[ii][jj] += p[ii] * vv[jj];
        }
#pragma unroll
        for (int ii = 0; ii < 4; ii++) {
            int d = ty * 4 + ii;
            size_t addr = attbase + (size_t)(h * 64 + d) * 4096 + nn0 + tx * 4;
            float4 w4 = make_float4(o[ii][0], o[ii][1], o[ii][2], o[ii][3]);
            *(float4*)&g_att[addr] = w4;
        }
        __syncthreads();
    }
}

// ---------------------------------------------------------------------------
// Kernel 3: y = att^T @ Wproj + bias.   att stored [k=512][n=4096] per (s,b).
// ---------------------------------------------------------------------------
__global__ __launch_bounds__(256) void proj_gemm_kernel(
    const float* __restrict__ Wr, const float* __restrict__ br,
    const float* __restrict__ Wt, const float* __restrict__ bt,
    float* __restrict__ out)
{
    const int z = blockIdx.z;
    const int s = z >> 3;
    const int b = z & 7;
    const float* __restrict__ W    = s ? Wt : Wr;
    const float* __restrict__ bias = s ? bt : br;
    const float* __restrict__ A = g_att + ((size_t)(s * 8 + b)) * 2097152;

    const int m0 = blockIdx.x * 128;   // n
    const int c0 = blockIdx.y * 128;   // output channel

    __shared__ float As[16][128];
    __shared__ float Ws2[16][128];

    const int tid = threadIdx.x;
    const int ty = tid >> 4;   // m-group
    const int tx = tid & 15;   // c-group

    float acc[8][8];
#pragma unroll
    for (int i = 0; i < 8; i++)
#pragma unroll
        for (int j = 0; j < 8; j++) acc[i][j] = 0.f;

    for (int k0 = 0; k0 < 512; k0 += 16) {
#pragma unroll
        for (int it = 0; it < 2; it++) {
            int idx = tid + it * 256;
            int kk = idx >> 5;
            int mq = idx & 31;
            *(float4*)&As[kk][mq * 4]  = *(const float4*)&A[(size_t)(k0 + kk) * 4096 + m0 + mq * 4];
            *(float4*)&Ws2[kk][mq * 4] = *(const float4*)&W[(size_t)(k0 + kk) * 512 + c0 + mq * 4];
        }
        __syncthreads();
#pragma unroll
        for (int kk = 0; kk < 16; kk++) {
            float rm[8], rc[8];
#pragma unroll
            for (int i = 0; i < 8; i++) rm[i] = As[kk][ty * 8 + i];
#pragma unroll
            for (int j = 0; j < 8; j++) rc[j] = Ws2[kk][tx * 8 + j];
#pragma unroll
            for (int i = 0; i < 8; i++)
#pragma unroll
                for (int j = 0; j < 8; j++) acc[i][j] += rm[i] * rc[j];
        }
        __syncthreads();
    }

    float bj[8];
#pragma unroll
    for (int j = 0; j < 8; j++) bj[j] = bias[c0 + tx * 8 + j];

    const size_t obase = (size_t)s * 16777216 + (size_t)b * 4096 * 512;
#pragma unroll
    for (int i = 0; i < 8; i++) {
        int n = m0 + ty * 8 + i;
        size_t row = obase + (size_t)n * 512 + c0 + tx * 8;
        float4 v0 = make_float4(acc[i][0] + bj[0], acc[i][1] + bj[1],
                                acc[i][2] + bj[2], acc[i][3] + bj[3]);
        float4 v1 = make_float4(acc[i][4] + bj[4], acc[i][5] + bj[5],
                                acc[i][6] + bj[6], acc[i][7] + bj[7]);
        *(float4*)&out[row]     = v0;
        *(float4*)&out[row + 4] = v1;
    }
}

// ---------------------------------------------------------------------------
extern "C" void kernel_launch(void* const* d_in, const int* in_sizes, int n_in,
                              void* d_out, int out_size)
{
    const float* x        = (const float*)d_in[0];
    const float* x_d      = (const float*)d_in[1];
    const float* W_qkv_r  = (const float*)d_in[2];
    const float* W_qkv_T  = (const float*)d_in[3];
    const float* temp_r   = (const float*)d_in[4];
    const float* temp_T   = (const float*)d_in[5];
    const float* W_proj_r = (const float*)d_in[6];
    const float* b_proj_r = (const float*)d_in[7];
    const float* W_proj_T = (const float*)d_in[8];
    const float* b_proj_T = (const float*)d_in[9];
    float* out = (float*)d_out;

    // 1) QKV GEMMs (both streams)
    {
        dim3 grid(256, 12, 2);   // m tiles (32768/128), c tiles (1536/128), stream
        qkv_gemm_kernel<<<grid, 256>>>(x, x_d, W_qkv_r, W_qkv_T);
    }
    // 2) Cross attention per (s, b, h)
    {
        dim3 grid(64, 2);
        attn_kernel<<<grid, 256>>>(temp_r, temp_T);
    }
    // 3) Projection + bias -> d_out
    {
        dim3 grid(32, 4, 16);    // n tiles, c tiles, s*b
        proj_gemm_kernel<<<grid, 256>>>(W_proj_r, b_proj_r, W_proj_T, b_proj_T, out);
    }
}

// round 5
// speedup vs baseline: 1.3352x; 1.3352x over previous
#include <cuda_runtime.h>
#include <cuda_bf16.h>
#include <math.h>
#include <stdint.h>

// ---------------------------------------------------------------------------
// ChannelCrossAttention: qkv GEMM + channel (XCA) attention + proj GEMM.
// GEMMs on HMMA (mma.sync bf16, 3-term fp32-split). Attention fp32.
// NOTE: tcgen05 is unavailable (harness compiles to non-'a' PTX target).
// ---------------------------------------------------------------------------

// scratch: qkv[s][w][b][h*64+d][n]
__device__ float g_qkv[2u * 3u * 8u * 512u * 4096u];   // 402 MB
// attention output, [s][b][k=h*64+d][n]
__device__ float g_att[2u * 8u * 512u * 4096u];        // 134 MB
// pre-transposed / bf16-split weights: [s][c][kpair] packed 2xbf16 per u32
__device__ uint32_t g_wq_hi[2u * 1536u * 256u];
__device__ uint32_t g_wq_lo[2u * 1536u * 256u];
__device__ uint32_t g_wp_hi[2u * 512u * 256u];
__device__ uint32_t g_wp_lo[2u * 512u * 256u];

// ---------------------------------------------------------------------------
__device__ __forceinline__ uint32_t smem_u32(const void* p) {
    uint32_t a;
    asm("{ .reg .u64 t; cvta.to.shared.u64 t, %1; cvt.u32.u64 %0, t; }" : "=r"(a) : "l"(p));
    return a;
}
__device__ __forceinline__ uint32_t swz(uint32_t off) { return off ^ ((off >> 3) & 0x70); }

__device__ __forceinline__ void ldmx4(uint32_t& r0, uint32_t& r1, uint32_t& r2, uint32_t& r3,
                                      uint32_t addr) {
    asm volatile("ldmatrix.sync.aligned.m8n8.x4.shared.b16 {%0,%1,%2,%3}, [%4];"
        : "=r"(r0), "=r"(r1), "=r"(r2), "=r"(r3) : "r"(addr));
}
__device__ __forceinline__ void mma16816(float* c, const uint32_t* a, const uint32_t* b) {
    asm volatile("mma.sync.aligned.m16n8k16.row.col.f32.bf16.bf16.f32 "
        "{%0,%1,%2,%3}, {%4,%5,%6,%7}, {%8,%9}, {%0,%1,%2,%3};"
        : "+f"(c[0]), "+f"(c[1]), "+f"(c[2]), "+f"(c[3])
        : "r"(a[0]), "r"(a[1]), "r"(a[2]), "r"(a[3]), "r"(b[0]), "r"(b[1]));
}

// fp32 -> (hi, lo) bf16 pair packing for two consecutive elements
__device__ __forceinline__ void cvt2(float a, float b, uint32_t& hi, uint32_t& lo) {
    __nv_bfloat16 ha = __float2bfloat16(a);
    __nv_bfloat16 hb = __float2bfloat16(b);
    float ra = a - __bfloat162float(ha);
    float rb = b - __bfloat162float(hb);
    __nv_bfloat16 la = __float2bfloat16(ra);
    __nv_bfloat16 lb = __float2bfloat16(rb);
    hi = (uint32_t)__bfloat16_as_ushort(ha) | ((uint32_t)__bfloat16_as_ushort(hb) << 16);
    lo = (uint32_t)__bfloat16_as_ushort(la) | ((uint32_t)__bfloat16_as_ushort(lb) << 16);
}

// smem regions (bytes from aligned base): A/B tiles 128 rows x 64 k bf16 (=128B/row)
#define S_AHI 0
#define S_ALO 16384
#define S_BHI 32768
#define S_BLO 49152
#define GEMM_SMEM_BYTES (65536 + 1024)

// ---------------------------------------------------------------------------
// Kernel 0: weight prep — transpose + bf16 hi/lo split (tiny)
// ---------------------------------------------------------------------------
__global__ __launch_bounds__(256) void prep_weights_kernel(
    const float* __restrict__ Wq_r, const float* __restrict__ Wq_T,
    const float* __restrict__ Wp_r, const float* __restrict__ Wp_T)
{
    int idx = blockIdx.x * 256 + threadIdx.x;
    const int TQ = 2 * 1536 * 256;
    const int TP = 2 * 512 * 256;
    if (idx < TQ) {
        int s = idx / (1536 * 256);
        int r = idx % (1536 * 256);
        int c = r >> 8, kp = r & 255;
        const float* W = s ? Wq_T : Wq_r;
        float w0 = W[(size_t)(2 * kp) * 1536 + c];
        float w1 = W[(size_t)(2 * kp + 1) * 1536 + c];
        uint32_t hi, lo; cvt2(w0, w1, hi, lo);
        g_wq_hi[idx] = hi; g_wq_lo[idx] = lo;
    } else if (idx < TQ + TP) {
        int i2 = idx - TQ;
        int s = i2 / (512 * 256);
        int r = i2 % (512 * 256);
        int c = r >> 8, kp = r & 255;
        const float* W = s ? Wp_T : Wp_r;
        float w0 = W[(size_t)(2 * kp) * 512 + c];
        float w1 = W[(size_t)(2 * kp + 1) * 512 + c];
        uint32_t hi, lo; cvt2(w0, w1, hi, lo);
        g_wp_hi[i2] = hi; g_wp_lo[i2] = lo;
    }
}

// ---------------------------------------------------------------------------
// Shared mainloop piece: given filled smem chunk, accumulate 3-term MMA.
// Warp layout: wm = wid&1 (2 x 64 rows), wn = wid>>1 (4 x 32 cols).
// ---------------------------------------------------------------------------
__device__ __forceinline__ void mma_chunk(char* ab, uint32_t sb,
                                          int wm, int wn, int lane,
                                          float acc[4][4][4])
{
    const int aRow  = wm * 64 + (lane & 15);
    const int aColb = (lane >> 4) * 16;
    const int bRow  = wn * 32 + (lane & 7) + ((lane >> 4) & 1) * 8;
    const int bColb = ((lane >> 3) & 1) * 16;
#pragma unroll
    for (int kk = 0; kk < 4; kk++) {
        uint32_t a[4][4], bh[4][2], bl[4][2];
#pragma unroll
        for (int mt = 0; mt < 4; mt++)
            ldmx4(a[mt][0], a[mt][1], a[mt][2], a[mt][3],
                  sb + S_AHI + swz((uint32_t)((aRow + mt * 16) * 128 + aColb + kk * 32)));
        ldmx4(bh[0][0], bh[0][1], bh[1][0], bh[1][1],
              sb + S_BHI + swz((uint32_t)(bRow * 128 + bColb + kk * 32)));
        ldmx4(bh[2][0], bh[2][1], bh[3][0], bh[3][1],
              sb + S_BHI + swz((uint32_t)((bRow + 16) * 128 + bColb + kk * 32)));
        ldmx4(bl[0][0], bl[0][1], bl[1][0], bl[1][1],
              sb + S_BLO + swz((uint32_t)(bRow * 128 + bColb + kk * 32)));
        ldmx4(bl[2][0], bl[2][1], bl[3][0], bl[3][1],
              sb + S_BLO + swz((uint32_t)((bRow + 16) * 128 + bColb + kk * 32)));
#pragma unroll
        for (int mt = 0; mt < 4; mt++)
#pragma unroll
            for (int nt = 0; nt < 4; nt++) {
                mma16816(acc[mt][nt], a[mt], bh[nt]);
                mma16816(acc[mt][nt], a[mt], bl[nt]);
            }
        // reuse a[] for A_lo
#pragma unroll
        for (int mt = 0; mt < 4; mt++)
            ldmx4(a[mt][0], a[mt][1], a[mt][2], a[mt][3],
                  sb + S_ALO + swz((uint32_t)((aRow + mt * 16) * 128 + aColb + kk * 32)));
#pragma unroll
        for (int mt = 0; mt < 4; mt++)
#pragma unroll
            for (int nt = 0; nt < 4; nt++)
                mma16816(acc[mt][nt], a[mt], bh[nt]);
    }
}

// ---------------------------------------------------------------------------
// Kernel 1: qkv GEMM.  D[m=token 128][n=channel 128], K=512.
// ---------------------------------------------------------------------------
__global__ __launch_bounds__(256) void qkv_mma_kernel(
    const float* __restrict__ x, const float* __restrict__ x_d)
{
    extern __shared__ char dsm[];
    uint32_t sbr = smem_u32(dsm);
    uint32_t sb = (sbr + 1023) & ~1023u;
    char* ab = dsm + (sb - sbr);

    const int tid = threadIdx.x;
    const int wid = tid >> 5;
    const int lane = tid & 31;
    const int wm = wid & 1, wn = wid >> 1;
    const int s = blockIdx.z;
    const float* __restrict__ X = s ? x_d : x;
    const uint32_t* __restrict__ WH = g_wq_hi + (size_t)s * 1536 * 256;
    const uint32_t* __restrict__ WL = g_wq_lo + (size_t)s * 1536 * 256;
    const int m0 = blockIdx.x * 128;
    const int c0 = blockIdx.y * 128;
    const int b = m0 >> 12, n0 = m0 & 4095;

    float acc[4][4][4];
#pragma unroll
    for (int i = 0; i < 4; i++)
#pragma unroll
        for (int j = 0; j < 4; j++)
#pragma unroll
            for (int r = 0; r < 4; r++) acc[i][j][r] = 0.f;

    for (int chunk = 0; chunk < 8; chunk++) {
        const int k0 = chunk * 64;
        // A fill: 128 tokens x 64 k (fp32 -> hi/lo)
#pragma unroll
        for (int it = 0; it < 16; it++) {
            int idx = tid + it * 256;
            int r = idx >> 5, kp = idx & 31;
            float2 v = *(const float2*)&X[(size_t)(m0 + r) * 512 + k0 + kp * 2];
            uint32_t hi, lo; cvt2(v.x, v.y, hi, lo);
            uint32_t off = swz((uint32_t)(r * 128 + kp * 4));
            *(uint32_t*)(ab + S_AHI + off) = hi;
            *(uint32_t*)(ab + S_ALO + off) = lo;
        }
        // B fill: pre-split weights (rows = channels)
#pragma unroll
        for (int it = 0; it < 16; it++) {
            int idx = tid + it * 256;
            int r = idx >> 5, kp = idx & 31;
            uint32_t hi = WH[(size_t)(c0 + r) * 256 + (k0 >> 1) + kp];
            uint32_t lo = WL[(size_t)(c0 + r) * 256 + (k0 >> 1) + kp];
            uint32_t off = swz((uint32_t)(r * 128 + kp * 4));
            *(uint32_t*)(ab + S_BHI + off) = hi;
            *(uint32_t*)(ab + S_BLO + off) = lo;
        }
        __syncthreads();
        mma_chunk(ab, sb, wm, wn, lane, acc);
        __syncthreads();
    }

    // epilogue: transpose to [channel][token] via smem, coalesced stores
    float* sT = (float*)ab;   // 64 x 136 fp32
#pragma unroll
    for (int p = 0; p < 2; p++) {
        if ((wn >> 1) == p) {
            int mbase = wm * 64 + (lane >> 2);
            int nbase = (wn & 1) * 32 + 2 * (lane & 3);
#pragma unroll
            for (int mt = 0; mt < 4; mt++)
#pragma unroll
                for (int nt = 0; nt < 4; nt++) {
                    int m = mbase + mt * 16;
                    int nl = nbase + nt * 8;
                    sT[nl * 136 + m]             = acc[mt][nt][0];
                    sT[(nl + 1) * 136 + m]       = acc[mt][nt][1];
                    sT[nl * 136 + m + 8]         = acc[mt][nt][2];
                    sT[(nl + 1) * 136 + m + 8]   = acc[mt][nt][3];
                }
        }
        __syncthreads();
#pragma unroll
        for (int it = 0; it < 8; it++) {
            int idx = tid + it * 256;
            int nrow = idx >> 5, m4 = (idx & 31) * 4;
            int c = c0 + p * 64 + nrow;
            int which = c >> 9;
            int rem = c & 511;
            float4 v = *(float4*)&sT[nrow * 136 + m4];
            *(float4*)&g_qkv[((size_t)((s * 3 + which) * 8 + b)) * 2097152
                             + (size_t)rem * 4096 + n0 + m4] = v;
        }
        __syncthreads();
    }
}

// ---------------------------------------------------------------------------
// Kernel 2: attention per (s, b, h) — fp32.
// ---------------------------------------------------------------------------
__global__ __launch_bounds__(256) void attn_kernel(
    const float* __restrict__ temp_rgb, const float* __restrict__ temp_T)
{
    const int s  = blockIdx.y;
    const int bh = blockIdx.x;
    const int b = bh >> 3;
    const int h = bh & 7;
    const int so = s ^ 1;

    const float* __restrict__ q = g_qkv + ((size_t)((s  * 3 + 0) * 8 + b)) * 2097152 + (size_t)h * 64 * 4096;
    const float* __restrict__ k = g_qkv + ((size_t)((so * 3 + 1) * 8 + b)) * 2097152 + (size_t)h * 64 * 4096;
    const float* __restrict__ v = g_qkv + ((size_t)((so * 3 + 2) * 8 + b)) * 2097152 + (size_t)h * 64 * 4096;
    const float temp = (s ? temp_T : temp_rgb)[h];

    __shared__ float bufA[64 * 65];
    __shared__ float bufB[64 * 65];
    __shared__ float qn[64], kn[64];

    const int tid = threadIdx.x;
    const int ty = tid >> 4;
    const int tx = tid & 15;

    float acc[4][4];
#pragma unroll
    for (int i = 0; i < 4; i++)
#pragma unroll
        for (int j = 0; j < 4; j++) acc[i][j] = 0.f;
    float nacc = 0.f;

    for (int ch = 0; ch < 64; ch++) {
        const int nn0 = ch * 64;
#pragma unroll
        for (int it = 0; it < 4; it++) {
            int idx = tid + it * 256;
            int r  = idx >> 4;
            int nq = idx & 15;
            float4 a4 = *(const float4*)&q[(size_t)r * 4096 + nn0 + nq * 4];
            bufA[r * 65 + nq * 4 + 0] = a4.x;
            bufA[r * 65 + nq * 4 + 1] = a4.y;
            bufA[r * 65 + nq * 4 + 2] = a4.z;
            bufA[r * 65 + nq * 4 + 3] = a4.w;
            float4 b4 = *(const float4*)&k[(size_t)r * 4096 + nn0 + nq * 4];
            bufB[r * 65 + nq * 4 + 0] = b4.x;
            bufB[r * 65 + nq * 4 + 1] = b4.y;
            bufB[r * 65 + nq * 4 + 2] = b4.z;
            bufB[r * 65 + nq * 4 + 3] = b4.w;
        }
        __syncthreads();
#pragma unroll 8
        for (int nn = 0; nn < 64; nn++) {
            float rq[4], rk[4];
#pragma unroll
            for (int i = 0; i < 4; i++) rq[i] = bufA[(ty * 4 + i) * 65 + nn];
#pragma unroll
            for (int j = 0; j < 4; j++) rk[j] = bufB[(tx * 4 + j) * 65 + nn];
#pragma unroll
            for (int i = 0; i < 4; i++)
#pragma unroll
                for (int j = 0; j < 4; j++) acc[i][j] += rq[i] * rk[j];
        }
        if (tid < 64) {
            float s2 = 0.f;
#pragma unroll 8
            for (int nn = 0; nn < 64; nn++) { float a = bufA[tid * 65 + nn]; s2 += a * a; }
            nacc += s2;
        } else if (tid < 128) {
            int r = tid - 64;
            float s2 = 0.f;
#pragma unroll 8
            for (int nn = 0; nn < 64; nn++) { float a = bufB[r * 65 + nn]; s2 += a * a; }
            nacc += s2;
        }
        __syncthreads();
    }

    if (tid < 64)       qn[tid]      = sqrtf(nacc);
    else if (tid < 128) kn[tid - 64] = sqrtf(nacc);
#pragma unroll
    for (int i = 0; i < 4; i++)
#pragma unroll
        for (int j = 0; j < 4; j++)
            bufB[(ty * 4 + i) * 65 + tx * 4 + j] = acc[i][j];
    __syncthreads();

    if (tid < 64) {
        const int i = tid;
        const float qi = fmaxf(qn[i], 1e-12f);
        float mx = -1e30f;
        for (int j = 0; j < 64; j++) {
            float val = bufB[i * 65 + j] * temp / (qi * fmaxf(kn[j], 1e-12f));
            bufB[i * 65 + j] = val;
            mx = fmaxf(mx, val);
        }
        float sum = 0.f;
        for (int j = 0; j < 64; j++) {
            float e = __expf(bufB[i * 65 + j] - mx);
            bufB[i * 65 + j] = e;
            sum += e;
        }
        float inv = 1.f / sum;
        for (int j = 0; j < 64; j++) bufB[i * 65 + j] *= inv;
    }
    __syncthreads();

    const size_t attbase = ((size_t)(s * 8 + b)) * 2097152;
    for (int ch = 0; ch < 64; ch++) {
        const int nn0 = ch * 64;
#pragma unroll
        for (int it = 0; it < 4; it++) {
            int idx = tid + it * 256;
            int r  = idx >> 4;
            int nq = idx & 15;
            float4 a4 = *(const float4*)&v[(size_t)r * 4096 + nn0 + nq * 4];
            bufA[r * 65 + nq * 4 + 0] = a4.x;
            bufA[r * 65 + nq * 4 + 1] = a4.y;
            bufA[r * 65 + nq * 4 + 2] = a4.z;
            bufA[r * 65 + nq * 4 + 3] = a4.w;
        }
        __syncthreads();
        float o[4][4];
#pragma unroll
        for (int i = 0; i < 4; i++)
#pragma unroll
            for (int j = 0; j < 4; j++) o[i][j] = 0.f;
#pragma unroll 8
        for (int j = 0; j < 64; j++) {
            float p[4], vv[4];
#pragma unroll
            for (int ii = 0; ii < 4; ii++) p[ii] = bufB[(ty * 4 + ii) * 65 + j];
#pragma unroll
            for (int jj = 0; jj < 4; jj++) vv[jj] = bufA[j * 65 + tx * 4 + jj];
#pragma unroll
            for (int ii = 0; ii < 4; ii++)
#pragma unroll
                for (int jj = 0; jj < 4; jj++) o[ii][jj] += p[ii] * vv[jj];
        }
#pragma unroll
        for (int ii = 0; ii < 4; ii++) {
            int d = ty * 4 + ii;
            size_t addr = attbase + (size_t)(h * 64 + d) * 4096 + nn0 + tx * 4;
            float4 w4 = make_float4(o[ii][0], o[ii][1], o[ii][2], o[ii][3]);
            *(float4*)&g_att[addr] = w4;
        }
        __syncthreads();
    }
}

// ---------------------------------------------------------------------------
// Kernel 3: proj GEMM.  out[token][channel] = att^T @ W + b.
// ---------------------------------------------------------------------------
__global__ __launch_bounds__(256) void proj_mma_kernel(
    const float* __restrict__ br, const float* __restrict__ bt,
    float* __restrict__ out)
{
    extern __shared__ char dsm[];
    uint32_t sbr = smem_u32(dsm);
    uint32_t sb = (sbr + 1023) & ~1023u;
    char* ab = dsm + (sb - sbr);

    const int tid = threadIdx.x;
    const int wid = tid >> 5;
    const int lane = tid & 31;
    const int wm = wid & 1, wn = wid >> 1;
    const int z = blockIdx.z;
    const int s = z >> 3, b = z & 7;
    const float* __restrict__ A = g_att + ((size_t)(s * 8 + b)) * 2097152;   // [k][n]
    const uint32_t* __restrict__ WH = g_wp_hi + (size_t)s * 512 * 256;
    const uint32_t* __restrict__ WL = g_wp_lo + (size_t)s * 512 * 256;
    const float* __restrict__ bias = s ? bt : br;
    const int n0 = blockIdx.x * 128;
    const int c0 = blockIdx.y * 128;

    float acc[4][4][4];
#pragma unroll
    for (int i = 0; i < 4; i++)
#pragma unroll
        for (int j = 0; j < 4; j++)
#pragma unroll
            for (int r = 0; r < 4; r++) acc[i][j][r] = 0.f;

    for (int chunk = 0; chunk < 8; chunk++) {
        const int k0 = chunk * 64;
        // A fill: transpose att[k][n] -> rows token, cols k (hi/lo)
#pragma unroll
        for (int it = 0; it < 16; it++) {
            int idx = tid + it * 256;
            int kp = idx >> 7, n = idx & 127;
            float a0 = A[(size_t)(k0 + 2 * kp) * 4096 + n0 + n];
            float a1 = A[(size_t)(k0 + 2 * kp + 1) * 4096 + n0 + n];
            uint32_t hi, lo; cvt2(a0, a1, hi, lo);
            uint32_t off = swz((uint32_t)(n * 128 + kp * 4));
            *(uint32_t*)(ab + S_AHI + off) = hi;
            *(uint32_t*)(ab + S_ALO + off) = lo;
        }
        // B fill: pre-split proj weights
#pragma unroll
        for (int it = 0; it < 16; it++) {
            int idx = tid + it * 256;
            int r = idx >> 5, kp = idx & 31;
            uint32_t hi = WH[(size_t)(c0 + r) * 256 + (k0 >> 1) + kp];
            uint32_t lo = WL[(size_t)(c0 + r) * 256 + (k0 >> 1) + kp];
            uint32_t off = swz((uint32_t)(r * 128 + kp * 4));
            *(uint32_t*)(ab + S_BHI + off) = hi;
            *(uint32_t*)(ab + S_BLO + off) = lo;
        }
        __syncthreads();
        mma_chunk(ab, sb, wm, wn, lane, acc);
        __syncthreads();
    }

    // epilogue: [token][channel] with bias, via smem transpose
    float* sT = (float*)ab;   // 64 x 136 fp32
    float* outp = out + (size_t)(s * 8 + b) * 2097152;
#pragma unroll
    for (int p = 0; p < 2; p++) {
        if (wm == p) {
            int mbase = (lane >> 2);
            int nbase = wn * 32 + 2 * (lane & 3);
#pragma unroll
            for (int mt = 0; mt < 4; mt++)
#pragma unroll
                for (int nt = 0; nt < 4; nt++) {
                    int m = mbase + mt * 16;
                    int nc = nbase + nt * 8;
                    sT[m * 136 + nc]           = acc[mt][nt][0];
                    sT[m * 136 + nc + 1]       = acc[mt][nt][1];
                    sT[(m + 8) * 136 + nc]     = acc[mt][nt][2];
                    sT[(m + 8) * 136 + nc + 1] = acc[mt][nt][3];
                }
        }
        __syncthreads();
#pragma unroll
        for (int it = 0; it < 8; it++) {
            int idx = tid + it * 256;
            int mrow = idx >> 5, ch4 = (idx & 31) * 4;
            int tok = n0 + p * 64 + mrow;
            float4 v = *(float4*)&sT[mrow * 136 + ch4];
            float4 bb = *(const float4*)&bias[c0 + ch4];
            v.x += bb.x; v.y += bb.y; v.z += bb.z; v.w += bb.w;
            *(float4*)&outp[(size_t)tok * 512 + c0 + ch4] = v;
        }
        __syncthreads();
    }
}

// ---------------------------------------------------------------------------
extern "C" void kernel_launch(void* const* d_in, const int* in_sizes, int n_in,
                              void* d_out, int out_size)
{
    const float* x        = (const float*)d_in[0];
    const float* x_d      = (const float*)d_in[1];
    const float* W_qkv_r  = (const float*)d_in[2];
    const float* W_qkv_T  = (const float*)d_in[3];
    const float* temp_r   = (const float*)d_in[4];
    const float* temp_T   = (const float*)d_in[5];
    const float* W_proj_r = (const float*)d_in[6];
    const float* b_proj_r = (const float*)d_in[7];
    const float* W_proj_T = (const float*)d_in[8];
    const float* b_proj_T = (const float*)d_in[9];
    float* out = (float*)d_out;

    cudaFuncSetAttribute(qkv_mma_kernel,
        cudaFuncAttributeMaxDynamicSharedMemorySize, GEMM_SMEM_BYTES);
    cudaFuncSetAttribute(proj_mma_kernel,
        cudaFuncAttributeMaxDynamicSharedMemorySize, GEMM_SMEM_BYTES);

    // 0) weight transpose + bf16 split (tiny)
    prep_weights_kernel<<<4096, 256>>>(W_qkv_r, W_qkv_T, W_proj_r, W_proj_T);

    // 1) qkv GEMMs on HMMA
    {
        dim3 grid(256, 12, 2);   // m tiles (32768/128), c tiles (1536/128), stream
        qkv_mma_kernel<<<grid, 256, GEMM_SMEM_BYTES>>>(x, x_d);
    }
    // 2) cross attention (fp32)
    {
        dim3 grid(64, 2);
        attn_kernel<<<grid, 256>>>(temp_r, temp_T);
    }
    // 3) projection on HMMA
    {
        dim3 grid(32, 4, 16);    // n tiles, c tiles, s*b
        proj_mma_kernel<<<grid, 256, GEMM_SMEM_BYTES>>>(b_proj_r, b_proj_T, out);
    }
}

// round 6
// speedup vs baseline: 2.4608x; 1.8430x over previous
#include <cuda_runtime.h>
#include <cuda_bf16.h>
#include <math.h>
#include <stdint.h>

// ---------------------------------------------------------------------------
// ChannelCrossAttention: qkv GEMM + channel (XCA) attention + proj GEMM.
// GEMMs: HMMA bf16 3-term split, cp.async fills, 2 CTA/SM.
// Attention: chunk-parallel (partial Gram -> softmax reduce -> P@V).
// ---------------------------------------------------------------------------

// fp32 qkv for attention use: [s][w][b][h*64+d][n]
__device__ float g_qkv[2u * 3u * 8u * 512u * 4096u];          // 402 MB
// pre-split inputs/weights, packed 2xbf16 per u32, [row][kpair]
__device__ uint32_t g_x_hi[2u * 32768u * 256u];               // 64 MB
__device__ uint32_t g_x_lo[2u * 32768u * 256u];
__device__ uint32_t g_wq_hi[2u * 1536u * 256u];
__device__ uint32_t g_wq_lo[2u * 1536u * 256u];
__device__ uint32_t g_wp_hi[2u * 512u * 256u];
__device__ uint32_t g_wp_lo[2u * 512u * 256u];
// attention output pre-split for proj: [s][b][n][kpair]
__device__ uint32_t g_att_hi[2u * 8u * 4096u * 256u];         // 64 MB
__device__ uint32_t g_att_lo[2u * 8u * 4096u * 256u];
// attention intermediates
__device__ float g_pgram[128u * 8u * 4096u];                  // 16 MB
__device__ float g_pqss[128u * 8u * 64u];
__device__ float g_pkss[128u * 8u * 64u];
__device__ float g_prob[128u * 4096u];                        // 2 MB

// ---------------------------------------------------------------------------
__device__ __forceinline__ uint32_t smem_u32(const void* p) {
    uint32_t a;
    asm("{ .reg .u64 t; cvta.to.shared.u64 t, %1; cvt.u32.u64 %0, t; }" : "=r"(a) : "l"(p));
    return a;
}
__device__ __forceinline__ uint32_t swz(uint32_t off) { return off ^ ((off >> 3) & 0x70); }

__device__ __forceinline__ void ldmx4(uint32_t& r0, uint32_t& r1, uint32_t& r2, uint32_t& r3,
                                      uint32_t addr) {
    asm volatile("ldmatrix.sync.aligned.m8n8.x4.shared.b16 {%0,%1,%2,%3}, [%4];"
        : "=r"(r0), "=r"(r1), "=r"(r2), "=r"(r3) : "r"(addr));
}
__device__ __forceinline__ void mma16816(float* c, const uint32_t* a, const uint32_t* b) {
    asm volatile("mma.sync.aligned.m16n8k16.row.col.f32.bf16.bf16.f32 "
        "{%0,%1,%2,%3}, {%4,%5,%6,%7}, {%8,%9}, {%0,%1,%2,%3};"
        : "+f"(c[0]), "+f"(c[1]), "+f"(c[2]), "+f"(c[3])
        : "r"(a[0]), "r"(a[1]), "r"(a[2]), "r"(a[3]), "r"(b[0]), "r"(b[1]));
}
#define CP_ASYNC16(dst, src) \
    asm volatile("cp.async.cg.shared.global [%0], [%1], 16;" :: "r"(dst), "l"(src))
#define CP_COMMIT() asm volatile("cp.async.commit_group;")
#define CP_WAIT0()  asm volatile("cp.async.wait_group 0;")

__device__ __forceinline__ void cvt2(float a, float b, uint32_t& hi, uint32_t& lo) {
    __nv_bfloat16 ha = __float2bfloat16(a);
    __nv_bfloat16 hb = __float2bfloat16(b);
    float ra = a - __bfloat162float(ha);
    float rb = b - __bfloat162float(hb);
    __nv_bfloat16 la = __float2bfloat16(ra);
    __nv_bfloat16 lb = __float2bfloat16(rb);
    hi = (uint32_t)__bfloat16_as_ushort(ha) | ((uint32_t)__bfloat16_as_ushort(hb) << 16);
    lo = (uint32_t)__bfloat16_as_ushort(la) | ((uint32_t)__bfloat16_as_ushort(lb) << 16);
}

// smem regions: A/B tiles 128 rows x 64 k bf16 (=128B/row)
#define S_AHI 0
#define S_ALO 16384
#define S_BHI 32768
#define S_BLO 49152
#define GEMM_SMEM_BYTES (65536 + 1024)

// ---------------------------------------------------------------------------
// Prep: split X and weights into bf16 hi/lo packed [row][kpair]
// ---------------------------------------------------------------------------
__global__ __launch_bounds__(256) void prep_x_kernel(
    const float* __restrict__ x, const float* __restrict__ x_d)
{
    int idx = blockIdx.x * 256 + threadIdx.x;      // over 2*32768*256
    int s = idx >> 23;
    int r = idx & 0x7FFFFF;
    int m = r >> 8, kp = r & 255;
    const float* X = s ? x_d : x;
    float2 v = *(const float2*)&X[(size_t)m * 512 + kp * 2];
    uint32_t hi, lo; cvt2(v.x, v.y, hi, lo);
    g_x_hi[idx] = hi; g_x_lo[idx] = lo;
}

__global__ __launch_bounds__(256) void prep_w_kernel(
    const float* __restrict__ Wq_r, const float* __restrict__ Wq_T,
    const float* __restrict__ Wp_r, const float* __restrict__ Wp_T)
{
    int idx = blockIdx.x * 256 + threadIdx.x;
    const int TQ = 2 * 1536 * 256;
    const int TP = 2 * 512 * 256;
    if (idx < TQ) {
        int s = idx / (1536 * 256);
        int r = idx % (1536 * 256);
        int c = r >> 8, kp = r & 255;
        const float* W = s ? Wq_T : Wq_r;
        float w0 = W[(size_t)(2 * kp) * 1536 + c];
        float w1 = W[(size_t)(2 * kp + 1) * 1536 + c];
        uint32_t hi, lo; cvt2(w0, w1, hi, lo);
        g_wq_hi[idx] = hi; g_wq_lo[idx] = lo;
    } else if (idx < TQ + TP) {
        int i2 = idx - TQ;
        int s = i2 / (512 * 256);
        int r = i2 % (512 * 256);
        int c = r >> 8, kp = r & 255;
        const float* W = s ? Wp_T : Wp_r;
        float w0 = W[(size_t)(2 * kp) * 512 + c];
        float w1 = W[(size_t)(2 * kp + 1) * 512 + c];
        uint32_t hi, lo; cvt2(w0, w1, hi, lo);
        g_wp_hi[i2] = hi; g_wp_lo[i2] = lo;
    }
}

// ---------------------------------------------------------------------------
// MMA accumulate for one 64-K chunk in smem. Warp layout: wm=wid&1, wn=wid>>1.
// ---------------------------------------------------------------------------
__device__ __forceinline__ void mma_chunk(uint32_t sb, int wm, int wn, int lane,
                                          float acc[4][4][4])
{
    const int aRow  = wm * 64 + (lane & 15);
    const int aColb = (lane >> 4) * 16;
    const int bRow  = wn * 32 + (lane & 7) + ((lane >> 4) & 1) * 8;
    const int bColb = ((lane >> 3) & 1) * 16;
#pragma unroll
    for (int kk = 0; kk < 4; kk++) {
        uint32_t a[4][4], bh[4][2], bl[4][2];
#pragma unroll
        for (int mt = 0; mt < 4; mt++)
            ldmx4(a[mt][0], a[mt][1], a[mt][2], a[mt][3],
                  sb + S_AHI + swz((uint32_t)((aRow + mt * 16) * 128 + aColb + kk * 32)));
        ldmx4(bh[0][0], bh[0][1], bh[1][0], bh[1][1],
              sb + S_BHI + swz((uint32_t)(bRow * 128 + bColb + kk * 32)));
        ldmx4(bh[2][0], bh[2][1], bh[3][0], bh[3][1],
              sb + S_BHI + swz((uint32_t)((bRow + 16) * 128 + bColb + kk * 32)));
        ldmx4(bl[0][0], bl[0][1], bl[1][0], bl[1][1],
              sb + S_BLO + swz((uint32_t)(bRow * 128 + bColb + kk * 32)));
        ldmx4(bl[2][0], bl[2][1], bl[3][0], bl[3][1],
              sb + S_BLO + swz((uint32_t)((bRow + 16) * 128 + bColb + kk * 32)));
#pragma unroll
        for (int mt = 0; mt < 4; mt++)
#pragma unroll
            for (int nt = 0; nt < 4; nt++) {
                mma16816(acc[mt][nt], a[mt], bh[nt]);
                mma16816(acc[mt][nt], a[mt], bl[nt]);
            }
#pragma unroll
        for (int mt = 0; mt < 4; mt++)
            ldmx4(a[mt][0], a[mt][1], a[mt][2], a[mt][3],
                  sb + S_ALO + swz((uint32_t)((aRow + mt * 16) * 128 + aColb + kk * 32)));
#pragma unroll
        for (int mt = 0; mt < 4; mt++)
#pragma unroll
            for (int nt = 0; nt < 4; nt++)
                mma16816(acc[mt][nt], a[mt], bh[nt]);
    }
}

// cp.async fill of one chunk: A rows from (AH,AL)+aRowBase, B rows from (BH,BL)+bRowBase
__device__ __forceinline__ void fill_chunk(uint32_t sb, int tid, int kp0,
    const uint32_t* __restrict__ AH, const uint32_t* __restrict__ AL, size_t aBase,
    const uint32_t* __restrict__ BH, const uint32_t* __restrict__ BL, size_t bBase)
{
#pragma unroll
    for (int it = 0; it < 4; it++) {
        int idx = tid + it * 256;              // 0..1023
        int r = idx >> 3, c16 = idx & 7;
        uint32_t dsw = swz((uint32_t)(r * 128 + c16 * 16));
        size_t ao = aBase + (size_t)r * 256 + kp0 + c16 * 4;
        size_t bo = bBase + (size_t)r * 256 + kp0 + c16 * 4;
        CP_ASYNC16(sb + S_AHI + dsw, AH + ao);
        CP_ASYNC16(sb + S_ALO + dsw, AL + ao);
        CP_ASYNC16(sb + S_BHI + dsw, BH + bo);
        CP_ASYNC16(sb + S_BLO + dsw, BL + bo);
    }
    CP_COMMIT();
}

// ---------------------------------------------------------------------------
// Kernel 1: qkv GEMM.  D[m=token 128][c=channel 128], K=512.
// ---------------------------------------------------------------------------
__global__ __launch_bounds__(256, 2) void qkv_mma_kernel()
{
    extern __shared__ char dsm[];
    uint32_t sbr = smem_u32(dsm);
    uint32_t sb = (sbr + 1023) & ~1023u;
    char* ab = dsm + (sb - sbr);

    const int tid = threadIdx.x;
    const int wid = tid >> 5;
    const int lane = tid & 31;
    const int wm = wid & 1, wn = wid >> 1;
    const int s = blockIdx.z;
    const int m0 = blockIdx.x * 128;
    const int c0 = blockIdx.y * 128;
    const int b = m0 >> 12, n0 = m0 & 4095;

    const uint32_t* XH = g_x_hi; const uint32_t* XL = g_x_lo;
    const uint32_t* WH = g_wq_hi; const uint32_t* WL = g_wq_lo;
    const size_t aBase = ((size_t)s * 32768 + m0) * 256;
    const size_t bBase = ((size_t)s * 1536 + c0) * 256;

    float acc[4][4][4];
#pragma unroll
    for (int i = 0; i < 4; i++)
#pragma unroll
        for (int j = 0; j < 4; j++)
#pragma unroll
            for (int r = 0; r < 4; r++) acc[i][j][r] = 0.f;

    for (int chunk = 0; chunk < 8; chunk++) {
        fill_chunk(sb, tid, chunk * 32, XH, XL, aBase, WH, WL, bBase);
        CP_WAIT0();
        __syncthreads();
        mma_chunk(sb, wm, wn, lane, acc);
        __syncthreads();
    }

    // epilogue: transpose to [channel][token] via smem, coalesced stores
    float* sT = (float*)ab;   // 64 x 136 fp32
#pragma unroll
    for (int p = 0; p < 2; p++) {
        if ((wn >> 1) == p) {
            int mbase = wm * 64 + (lane >> 2);
            int nbase = (wn & 1) * 32 + 2 * (lane & 3);
#pragma unroll
            for (int mt = 0; mt < 4; mt++)
#pragma unroll
                for (int nt = 0; nt < 4; nt++) {
                    int m = mbase + mt * 16;
                    int nl = nbase + nt * 8;
                    sT[nl * 136 + m]             = acc[mt][nt][0];
                    sT[(nl + 1) * 136 + m]       = acc[mt][nt][1];
                    sT[nl * 136 + m + 8]         = acc[mt][nt][2];
                    sT[(nl + 1) * 136 + m + 8]   = acc[mt][nt][3];
                }
        }
        __syncthreads();
#pragma unroll
        for (int it = 0; it < 8; it++) {
            int idx = tid + it * 256;
            int nrow = idx >> 5, m4 = (idx & 31) * 4;
            int c = c0 + p * 64 + nrow;
            int which = c >> 9;
            int rem = c & 511;
            float4 v = *(float4*)&sT[nrow * 136 + m4];
            *(float4*)&g_qkv[((size_t)((s * 3 + which) * 8 + b)) * 2097152
                             + (size_t)rem * 4096 + n0 + m4] = v;
        }
        __syncthreads();
    }
}

// ---------------------------------------------------------------------------
// Kernel 2a: partial Gram + sumsq per (s,bh,chunk of 512 tokens)
// ---------------------------------------------------------------------------
__global__ __launch_bounds__(256) void attn_pass1_kernel()
{
    const int chunk = blockIdx.x;       // 0..7
    const int bh = blockIdx.y;          // b*8+h
    const int s  = blockIdx.z;
    const int b = bh >> 3, h = bh & 7;
    const int so = s ^ 1;
    const int g = s * 64 + bh;

    const float* __restrict__ q = g_qkv + ((size_t)((s  * 3 + 0) * 8 + b)) * 2097152 + (size_t)h * 262144;
    const float* __restrict__ k = g_qkv + ((size_t)((so * 3 + 1) * 8 + b)) * 2097152 + (size_t)h * 262144;

    __shared__ float bufA[64 * 65];
    __shared__ float bufB[64 * 65];

    const int tid = threadIdx.x;
    const int ty = tid >> 4;
    const int tx = tid & 15;

    float acc[4][4];
#pragma unroll
    for (int i = 0; i < 4; i++)
#pragma unroll
        for (int j = 0; j < 4; j++) acc[i][j] = 0.f;
    float nacc = 0.f;

    for (int sub = 0; sub < 8; sub++) {
        const int nn0 = chunk * 512 + sub * 64;
#pragma unroll
        for (int it = 0; it < 4; it++) {
            int idx = tid + it * 256;
            int r = idx >> 4, nq = idx & 15;
            float4 a4 = *(const float4*)&q[(size_t)r * 4096 + nn0 + nq * 4];
            bufA[r * 65 + nq * 4 + 0] = a4.x; bufA[r * 65 + nq * 4 + 1] = a4.y;
            bufA[r * 65 + nq * 4 + 2] = a4.z; bufA[r * 65 + nq * 4 + 3] = a4.w;
            float4 b4 = *(const float4*)&k[(size_t)r * 4096 + nn0 + nq * 4];
            bufB[r * 65 + nq * 4 + 0] = b4.x; bufB[r * 65 + nq * 4 + 1] = b4.y;
            bufB[r * 65 + nq * 4 + 2] = b4.z; bufB[r * 65 + nq * 4 + 3] = b4.w;
        }
        __syncthreads();
#pragma unroll 8
        for (int nn = 0; nn < 64; nn++) {
            float rq[4], rk[4];
#pragma unroll
            for (int i = 0; i < 4; i++) rq[i] = bufA[(ty * 4 + i) * 65 + nn];
#pragma unroll
            for (int j = 0; j < 4; j++) rk[j] = bufB[(tx * 4 + j) * 65 + nn];
#pragma unroll
            for (int i = 0; i < 4; i++)
#pragma unroll
                for (int j = 0; j < 4; j++) acc[i][j] += rq[i] * rk[j];
        }
        if (tid < 64) {
            float s2 = 0.f;
#pragma unroll 8
            for (int nn = 0; nn < 64; nn++) { float a = bufA[tid * 65 + nn]; s2 += a * a; }
            nacc += s2;
        } else if (tid < 128) {
            int r = tid - 64;
            float s2 = 0.f;
#pragma unroll 8
            for (int nn = 0; nn < 64; nn++) { float a = bufB[r * 65 + nn]; s2 += a * a; }
            nacc += s2;
        }
        __syncthreads();
    }

    const size_t gbase = (size_t)(g * 8 + chunk) * 4096;
#pragma unroll
    for (int i = 0; i < 4; i++) {
        float4 v = make_float4(acc[i][0], acc[i][1], acc[i][2], acc[i][3]);
        *(float4*)&g_pgram[gbase + (ty * 4 + i) * 64 + tx * 4] = v;
    }
    if (tid < 64)       g_pqss[(g * 8 + chunk) * 64 + tid] = nacc;
    else if (tid < 128) g_pkss[(g * 8 + chunk) * 64 + tid - 64] = nacc;
}

// ---------------------------------------------------------------------------
// Kernel 2b: reduce partials, softmax -> g_prob
// ---------------------------------------------------------------------------
__global__ __launch_bounds__(256) void attn_softmax_kernel(
    const float* __restrict__ temp_rgb, const float* __restrict__ temp_T)
{
    const int g = blockIdx.x;           // s*64 + b*8 + h
    const int s = g >> 6, h = g & 7;
    const float temp = (s ? temp_T : temp_rgb)[h];

    __shared__ float sP[64 * 65];
    __shared__ float qn[64], kn[64];
    const int tid = threadIdx.x;

#pragma unroll
    for (int it = 0; it < 16; it++) {
        int idx = tid + it * 256;
        int i = idx >> 6, j = idx & 63;
        float sum = 0.f;
#pragma unroll
        for (int c = 0; c < 8; c++) sum += g_pgram[(size_t)(g * 8 + c) * 4096 + idx];
        sP[i * 65 + j] = sum;
    }
    if (tid < 64) {
        float sq = 0.f;
#pragma unroll
        for (int c = 0; c < 8; c++) sq += g_pqss[(g * 8 + c) * 64 + tid];
        qn[tid] = sqrtf(sq);
    } else if (tid < 128) {
        float sk = 0.f;
#pragma unroll
        for (int c = 0; c < 8; c++) sk += g_pkss[(g * 8 + c) * 64 + tid - 64];
        kn[tid - 64] = sqrtf(sk);
    }
    __syncthreads();

    if (tid < 64) {
        const int i = tid;
        const float qi = fmaxf(qn[i], 1e-12f);
        float mx = -1e30f;
        for (int j = 0; j < 64; j++) {
            float val = sP[i * 65 + j] * temp / (qi * fmaxf(kn[j], 1e-12f));
            sP[i * 65 + j] = val;
            mx = fmaxf(mx, val);
        }
        float sum = 0.f;
        for (int j = 0; j < 64; j++) {
            float e = __expf(sP[i * 65 + j] - mx);
            sP[i * 65 + j] = e;
            sum += e;
        }
        float inv = 1.f / sum;
        for (int j = 0; j < 64; j++) sP[i * 65 + j] *= inv;
    }
    __syncthreads();
#pragma unroll
    for (int it = 0; it < 16; it++) {
        int idx = tid + it * 256;
        int i = idx >> 6, j = idx & 63;
        g_prob[(size_t)g * 4096 + idx] = sP[i * 65 + j];
    }
}

// ---------------------------------------------------------------------------
// Kernel 2c: out = P @ v per (s,bh,chunk); emit packed bf16 hi/lo [n][kpair]
// ---------------------------------------------------------------------------
__global__ __launch_bounds__(256) void attn_pass2_kernel()
{
    const int chunk = blockIdx.x;
    const int bh = blockIdx.y;
    const int s  = blockIdx.z;
    const int b = bh >> 3, h = bh & 7;
    const int so = s ^ 1;
    const int g = s * 64 + bh;

    const float* __restrict__ v = g_qkv + ((size_t)((so * 3 + 2) * 8 + b)) * 2097152 + (size_t)h * 262144;

    __shared__ float bufA[64 * 65];     // v subtile [e][n]
    __shared__ float sP[64 * 65];       // P [d][e]

    const int tid = threadIdx.x;
    const int ty = tid >> 4;            // n-group
    const int tx = tid & 15;            // d-group

#pragma unroll
    for (int it = 0; it < 16; it++) {
        int idx = tid + it * 256;
        int i = idx >> 6, j = idx & 63;
        sP[i * 65 + j] = g_prob[(size_t)g * 4096 + idx];
    }
    __syncthreads();

    const size_t obase = ((size_t)(s * 8 + b)) * 4096;
    for (int sub = 0; sub < 8; sub++) {
        const int nn0 = chunk * 512 + sub * 64;
#pragma unroll
        for (int it = 0; it < 4; it++) {
            int idx = tid + it * 256;
            int r = idx >> 4, nq = idx & 15;
            float4 a4 = *(const float4*)&v[(size_t)r * 4096 + nn0 + nq * 4];
            bufA[r * 65 + nq * 4 + 0] = a4.x; bufA[r * 65 + nq * 4 + 1] = a4.y;
            bufA[r * 65 + nq * 4 + 2] = a4.z; bufA[r * 65 + nq * 4 + 3] = a4.w;
        }
        __syncthreads();
        float o[4][4];                  // [n][d]
#pragma unroll
        for (int i = 0; i < 4; i++)
#pragma unroll
            for (int j = 0; j < 4; j++) o[i][j] = 0.f;
#pragma unroll 8
        for (int e = 0; e < 64; e++) {
            float rv[4], rp[4];
#pragma unroll
            for (int ii = 0; ii < 4; ii++) rv[ii] = bufA[e * 65 + ty * 4 + ii];
#pragma unroll
            for (int jj = 0; jj < 4; jj++) rp[jj] = sP[(tx * 4 + jj) * 65 + e];
#pragma unroll
            for (int ii = 0; ii < 4; ii++)
#pragma unroll
                for (int jj = 0; jj < 4; jj++) o[ii][jj] += rv[ii] * rp[jj];
        }
#pragma unroll
        for (int ii = 0; ii < 4; ii++) {
            int n = nn0 + ty * 4 + ii;
            size_t base = (obase + n) * 256 + h * 32 + tx * 2;
            uint32_t h0, l0, h1, l1;
            cvt2(o[ii][0], o[ii][1], h0, l0);
            cvt2(o[ii][2], o[ii][3], h1, l1);
            *(uint2*)&g_att_hi[base] = make_uint2(h0, h1);
            *(uint2*)&g_att_lo[base] = make_uint2(l0, l1);
        }
        __syncthreads();
    }
}

// ---------------------------------------------------------------------------
// Kernel 3: proj GEMM.  out[token][channel] = att @ W + b.
// ---------------------------------------------------------------------------
__global__ __launch_bounds__(256, 2) void proj_mma_kernel(
    const float* __restrict__ br, const float* __restrict__ bt,
    float* __restrict__ out)
{
    extern __shared__ char dsm[];
    uint32_t sbr = smem_u32(dsm);
    uint32_t sb = (sbr + 1023) & ~1023u;
    char* ab = dsm + (sb - sbr);

    const int tid = threadIdx.x;
    const int wid = tid >> 5;
    const int lane = tid & 31;
    const int wm = wid & 1, wn = wid >> 1;
    const int z = blockIdx.z;
    const int s = z >> 3, b = z & 7;
    const float* __restrict__ bias = s ? bt : br;
    const int n0 = blockIdx.x * 128;
    const int c0 = blockIdx.y * 128;

    const size_t aBase = (((size_t)(s * 8 + b)) * 4096 + n0) * 256;
    const size_t bBase = ((size_t)s * 512 + c0) * 256;

    float acc[4][4][4];
#pragma unroll
    for (int i = 0; i < 4; i++)
#pragma unroll
        for (int j = 0; j < 4; j++)
#pragma unroll
            for (int r = 0; r < 4; r++) acc[i][j][r] = 0.f;

    for (int chunk = 0; chunk < 8; chunk++) {
        fill_chunk(sb, tid, chunk * 32, g_att_hi, g_att_lo, aBase, g_wp_hi, g_wp_lo, bBase);
        CP_WAIT0();
        __syncthreads();
        mma_chunk(sb, wm, wn, lane, acc);
        __syncthreads();
    }

    // epilogue: [token][channel] with bias, via smem transpose
    float* sT = (float*)ab;   // 64 x 136 fp32
    float* outp = out + (size_t)(s * 8 + b) * 2097152;
#pragma unroll
    for (int p = 0; p < 2; p++) {
        if (wm == p) {
            int mbase = (lane >> 2);
            int nbase = wn * 32 + 2 * (lane & 3);
#pragma unroll
            for (int mt = 0; mt < 4; mt++)
#pragma unroll
                for (int nt = 0; nt < 4; nt++) {
                    int m = mbase + mt * 16;
                    int nc = nbase + nt * 8;
                    sT[m * 136 + nc]           = acc[mt][nt][0];
                    sT[m * 136 + nc + 1]       = acc[mt][nt][1];
                    sT[(m + 8) * 136 + nc]     = acc[mt][nt][2];
                    sT[(m + 8) * 136 + nc + 1] = acc[mt][nt][3];
                }
        }
        __syncthreads();
#pragma unroll
        for (int it = 0; it < 8; it++) {
            int idx = tid + it * 256;
            int mrow = idx >> 5, ch4 = (idx & 31) * 4;
            int tok = n0 + p * 64 + mrow;
            float4 vv = *(float4*)&sT[mrow * 136 + ch4];
            float4 bb = *(const float4*)&bias[c0 + ch4];
            vv.x += bb.x; vv.y += bb.y; vv.z += bb.z; vv.w += bb.w;
            *(float4*)&outp[(size_t)tok * 512 + c0 + ch4] = vv;
        }
        __syncthreads();
    }
}

// ---------------------------------------------------------------------------
extern "C" void kernel_launch(void* const* d_in, const int* in_sizes, int n_in,
                              void* d_out, int out_size)
{
    const float* x        = (const float*)d_in[0];
    const float* x_d      = (const float*)d_in[1];
    const float* W_qkv_r  = (const float*)d_in[2];
    const float* W_qkv_T  = (const float*)d_in[3];
    const float* temp_r   = (const float*)d_in[4];
    const float* temp_T   = (const float*)d_in[5];
    const float* W_proj_r = (const float*)d_in[6];
    const float* b_proj_r = (const float*)d_in[7];
    const float* W_proj_T = (const float*)d_in[8];
    const float* b_proj_T = (const float*)d_in[9];
    float* out = (float*)d_out;

    cudaFuncSetAttribute(qkv_mma_kernel,
        cudaFuncAttributeMaxDynamicSharedMemorySize, GEMM_SMEM_BYTES);
    cudaFuncSetAttribute(proj_mma_kernel,
        cudaFuncAttributeMaxDynamicSharedMemorySize, GEMM_SMEM_BYTES);

    // 0) pre-split inputs + weights
    prep_x_kernel<<<65536, 256>>>(x, x_d);
    prep_w_kernel<<<4096, 256>>>(W_qkv_r, W_qkv_T, W_proj_r, W_proj_T);

    // 1) qkv GEMMs
    {
        dim3 grid(256, 12, 2);
        qkv_mma_kernel<<<grid, 256, GEMM_SMEM_BYTES>>>();
    }
    // 2) attention: partial Gram -> softmax -> P@V
    {
        dim3 g1(8, 64, 2);
        attn_pass1_kernel<<<g1, 256>>>();
        attn_softmax_kernel<<<128, 256>>>(temp_r, temp_T);
        attn_pass2_kernel<<<g1, 256>>>();
    }
    // 3) projection
    {
        dim3 grid(32, 4, 16);
        proj_mma_kernel<<<grid, 256, GEMM_SMEM_BYTES>>>(b_proj_r, b_proj_T, out);
    }
}

// round 7
// speedup vs baseline: 2.9296x; 1.1905x over previous
#include <cuda_runtime.h>
#include <cuda_bf16.h>
#include <math.h>
#include <stdint.h>

// ---------------------------------------------------------------------------
// ChannelCrossAttention — all GEMM-like work on HMMA bf16 3-term split.
//   qkv GEMM -> (q,k channel-major bf16 hi/lo + norms, v token-major hi/lo)
//   Gram HMMA (partials) -> softmax (norm fold, emits P hi/lo)
//   P@V HMMA -> att token-major hi/lo -> proj HMMA -> out
// ---------------------------------------------------------------------------

// pre-split inputs/weights, packed 2xbf16 per u32
__device__ uint32_t g_x_hi[2u * 32768u * 256u];               // [s][m][kpair]
__device__ uint32_t g_x_lo[2u * 32768u * 256u];
__device__ uint32_t g_wq_hi[2u * 1536u * 256u];
__device__ uint32_t g_wq_lo[2u * 1536u * 256u];
__device__ uint32_t g_wp_hi[2u * 512u * 256u];
__device__ uint32_t g_wp_lo[2u * 512u * 256u];
// q,k channel-major: [s][w(q=0,k=1)][b][c 512][npair 2048]
__device__ uint32_t g_qk_hi[2u * 2u * 8u * 512u * 2048u];     // 134 MB
__device__ uint32_t g_qk_lo[2u * 2u * 8u * 512u * 2048u];
// v token-major: [s][b][n 4096][cpair 256]
__device__ uint32_t g_v_hi[2u * 8u * 4096u * 256u];           // 67 MB
__device__ uint32_t g_v_lo[2u * 8u * 4096u * 256u];
// attention out token-major: [s][b][n][kpair 256]
__device__ uint32_t g_att_hi[2u * 8u * 4096u * 256u];
__device__ uint32_t g_att_lo[2u * 8u * 4096u * 256u];
// per-channel sumsq partials: [s][w][b][c 512][mtile 32]
__device__ float g_nrm[2u * 2u * 8u * 512u * 32u];
// Gram partials [g 128][chunk 8][64*64]
__device__ float g_pgram[128u * 8u * 4096u];
// P packed [g][d 64][epair 32]
__device__ uint32_t g_p_hi[128u * 2048u];
__device__ uint32_t g_p_lo[128u * 2048u];

// ---------------------------------------------------------------------------
__device__ __forceinline__ uint32_t smem_u32(const void* p) {
    uint32_t a;
    asm("{ .reg .u64 t; cvta.to.shared.u64 t, %1; cvt.u32.u64 %0, t; }" : "=r"(a) : "l"(p));
    return a;
}
__device__ __forceinline__ uint32_t swz(uint32_t off) { return off ^ ((off >> 3) & 0x70); }

__device__ __forceinline__ void ldmx4(uint32_t& r0, uint32_t& r1, uint32_t& r2, uint32_t& r3,
                                      uint32_t addr) {
    asm volatile("ldmatrix.sync.aligned.m8n8.x4.shared.b16 {%0,%1,%2,%3}, [%4];"
        : "=r"(r0), "=r"(r1), "=r"(r2), "=r"(r3) : "r"(addr));
}
__device__ __forceinline__ void mma16816(float* c, const uint32_t* a, const uint32_t* b) {
    asm volatile("mma.sync.aligned.m16n8k16.row.col.f32.bf16.bf16.f32 "
        "{%0,%1,%2,%3}, {%4,%5,%6,%7}, {%8,%9}, {%0,%1,%2,%3};"
        : "+f"(c[0]), "+f"(c[1]), "+f"(c[2]), "+f"(c[3])
        : "r"(a[0]), "r"(a[1]), "r"(a[2]), "r"(a[3]), "r"(b[0]), "r"(b[1]));
}
#define CP_ASYNC16(dst, src) \
    asm volatile("cp.async.cg.shared.global [%0], [%1], 16;" :: "r"(dst), "l"(src))
#define CP_COMMIT() asm volatile("cp.async.commit_group;")
#define CP_WAIT0()  asm volatile("cp.async.wait_group 0;")

__device__ __forceinline__ void cvt2(float a, float b, uint32_t& hi, uint32_t& lo) {
    __nv_bfloat16 ha = __float2bfloat16(a);
    __nv_bfloat16 hb = __float2bfloat16(b);
    float ra = a - __bfloat162float(ha);
    float rb = b - __bfloat162float(hb);
    __nv_bfloat16 la = __float2bfloat16(ra);
    __nv_bfloat16 lb = __float2bfloat16(rb);
    hi = (uint32_t)__bfloat16_as_ushort(ha) | ((uint32_t)__bfloat16_as_ushort(hb) << 16);
    lo = (uint32_t)__bfloat16_as_ushort(la) | ((uint32_t)__bfloat16_as_ushort(lb) << 16);
}

// GEMM smem regions: A/B tiles 128 rows x 64 k bf16 (=128B/row)
#define S_AHI 0
#define S_ALO 16384
#define S_BHI 32768
#define S_BLO 49152
#define GEMM_SMEM_BYTES (65536 + 1024)
// Gram smem: 4 x (64 rows x 128B) = 32KB
#define S1_AHI 0
#define S1_ALO 8192
#define S1_BHI 16384
#define S1_BLO 24576
#define GRAM_SMEM_BYTES (32768 + 1024)
// P@V smem: A 2x16KB + B 2x8KB = 48KB
#define S2_AHI 0
#define S2_ALO 16384
#define S2_BHI 32768
#define S2_BLO 40960
#define PV_SMEM_BYTES (49152 + 1024)

// ---------------------------------------------------------------------------
// Prep kernels
// ---------------------------------------------------------------------------
__global__ __launch_bounds__(256) void prep_x_kernel(
    const float* __restrict__ x, const float* __restrict__ x_d)
{
    int idx = blockIdx.x * 256 + threadIdx.x;
    int s = idx >> 23;
    int r = idx & 0x7FFFFF;
    int m = r >> 8, kp = r & 255;
    const float* X = s ? x_d : x;
    float2 v = *(const float2*)&X[(size_t)m * 512 + kp * 2];
    uint32_t hi, lo; cvt2(v.x, v.y, hi, lo);
    g_x_hi[idx] = hi; g_x_lo[idx] = lo;
}

__global__ __launch_bounds__(256) void prep_w_kernel(
    const float* __restrict__ Wq_r, const float* __restrict__ Wq_T,
    const float* __restrict__ Wp_r, const float* __restrict__ Wp_T)
{
    int idx = blockIdx.x * 256 + threadIdx.x;
    const int TQ = 2 * 1536 * 256;
    const int TP = 2 * 512 * 256;
    if (idx < TQ) {
        int s = idx / (1536 * 256);
        int r = idx % (1536 * 256);
        int c = r >> 8, kp = r & 255;
        const float* W = s ? Wq_T : Wq_r;
        float w0 = W[(size_t)(2 * kp) * 1536 + c];
        float w1 = W[(size_t)(2 * kp + 1) * 1536 + c];
        uint32_t hi, lo; cvt2(w0, w1, hi, lo);
        g_wq_hi[idx] = hi; g_wq_lo[idx] = lo;
    } else if (idx < TQ + TP) {
        int i2 = idx - TQ;
        int s = i2 / (512 * 256);
        int r = i2 % (512 * 256);
        int c = r >> 8, kp = r & 255;
        const float* W = s ? Wp_T : Wp_r;
        float w0 = W[(size_t)(2 * kp) * 512 + c];
        float w1 = W[(size_t)(2 * kp + 1) * 512 + c];
        uint32_t hi, lo; cvt2(w0, w1, hi, lo);
        g_wp_hi[i2] = hi; g_wp_lo[i2] = lo;
    }
}

// ---------------------------------------------------------------------------
// 128x128 3-term MMA chunk (shared by qkv/proj). wm=wid&1, wn=wid>>1.
// ---------------------------------------------------------------------------
__device__ __forceinline__ void mma_chunk(uint32_t sb, int wm, int wn, int lane,
                                          float acc[4][4][4])
{
    const int aRow  = wm * 64 + (lane & 15);
    const int aColb = (lane >> 4) * 16;
    const int bRow  = wn * 32 + (lane & 7) + ((lane >> 4) & 1) * 8;
    const int bColb = ((lane >> 3) & 1) * 16;
#pragma unroll
    for (int kk = 0; kk < 4; kk++) {
        uint32_t a[4][4], bh[4][2], bl[4][2];
#pragma unroll
        for (int mt = 0; mt < 4; mt++)
            ldmx4(a[mt][0], a[mt][1], a[mt][2], a[mt][3],
                  sb + S_AHI + swz((uint32_t)((aRow + mt * 16) * 128 + aColb + kk * 32)));
        ldmx4(bh[0][0], bh[0][1], bh[1][0], bh[1][1],
              sb + S_BHI + swz((uint32_t)(bRow * 128 + bColb + kk * 32)));
        ldmx4(bh[2][0], bh[2][1], bh[3][0], bh[3][1],
              sb + S_BHI + swz((uint32_t)((bRow + 16) * 128 + bColb + kk * 32)));
        ldmx4(bl[0][0], bl[0][1], bl[1][0], bl[1][1],
              sb + S_BLO + swz((uint32_t)(bRow * 128 + bColb + kk * 32)));
        ldmx4(bl[2][0], bl[2][1], bl[3][0], bl[3][1],
              sb + S_BLO + swz((uint32_t)((bRow + 16) * 128 + bColb + kk * 32)));
#pragma unroll
        for (int mt = 0; mt < 4; mt++)
#pragma unroll
            for (int nt = 0; nt < 4; nt++) {
                mma16816(acc[mt][nt], a[mt], bh[nt]);
                mma16816(acc[mt][nt], a[mt], bl[nt]);
            }
#pragma unroll
        for (int mt = 0; mt < 4; mt++)
            ldmx4(a[mt][0], a[mt][1], a[mt][2], a[mt][3],
                  sb + S_ALO + swz((uint32_t)((aRow + mt * 16) * 128 + aColb + kk * 32)));
#pragma unroll
        for (int mt = 0; mt < 4; mt++)
#pragma unroll
            for (int nt = 0; nt < 4; nt++)
                mma16816(acc[mt][nt], a[mt], bh[nt]);
    }
}

__device__ __forceinline__ void fill_chunk(uint32_t sb, int tid, int kp0,
    const uint32_t* __restrict__ AH, const uint32_t* __restrict__ AL, size_t aBase,
    const uint32_t* __restrict__ BH, const uint32_t* __restrict__ BL, size_t bBase)
{
#pragma unroll
    for (int it = 0; it < 4; it++) {
        int idx = tid + it * 256;
        int r = idx >> 3, c16 = idx & 7;
        uint32_t dsw = swz((uint32_t)(r * 128 + c16 * 16));
        size_t ao = aBase + (size_t)r * 256 + kp0 + c16 * 4;
        size_t bo = bBase + (size_t)r * 256 + kp0 + c16 * 4;
        CP_ASYNC16(sb + S_AHI + dsw, AH + ao);
        CP_ASYNC16(sb + S_ALO + dsw, AL + ao);
        CP_ASYNC16(sb + S_BHI + dsw, BH + bo);
        CP_ASYNC16(sb + S_BLO + dsw, BL + bo);
    }
    CP_COMMIT();
}

// ---------------------------------------------------------------------------
// Kernel 1: qkv GEMM. Epilogue emits bf16 operands for attention.
// ---------------------------------------------------------------------------
__global__ __launch_bounds__(256, 2) void qkv_mma_kernel()
{
    extern __shared__ char dsm[];
    uint32_t sbr = smem_u32(dsm);
    uint32_t sb = (sbr + 1023) & ~1023u;
    char* ab = dsm + (sb - sbr);

    const int tid = threadIdx.x;
    const int wid = tid >> 5;
    const int lane = tid & 31;
    const int wm = wid & 1, wn = wid >> 1;
    const int s = blockIdx.z;
    const int m0 = blockIdx.x * 128;
    const int c0 = blockIdx.y * 128;
    const int b = m0 >> 12, n0 = m0 & 4095;
    const int which = c0 >> 9;          // 0=q 1=k 2=v (uniform per CTA)

    const size_t aBase = ((size_t)s * 32768 + m0) * 256;
    const size_t bBase = ((size_t)s * 1536 + c0) * 256;

    float acc[4][4][4];
#pragma unroll
    for (int i = 0; i < 4; i++)
#pragma unroll
        for (int j = 0; j < 4; j++)
#pragma unroll
            for (int r = 0; r < 4; r++) acc[i][j][r] = 0.f;

    for (int chunk = 0; chunk < 8; chunk++) {
        fill_chunk(sb, tid, chunk * 32, g_x_hi, g_x_lo, aBase, g_wq_hi, g_wq_lo, bBase);
        CP_WAIT0();
        __syncthreads();
        mma_chunk(sb, wm, wn, lane, acc);
        __syncthreads();
    }

    if (which == 2) {
        // v: pack channel-pairs directly from frags -> token-major [n][cpair]
        const size_t vb = (size_t)(s * 8 + b) * 4096;
        const int cpb = (c0 - 1024) >> 1;
#pragma unroll
        for (int mt = 0; mt < 4; mt++) {
            int t = n0 + wm * 64 + mt * 16 + (lane >> 2);
#pragma unroll
            for (int nt = 0; nt < 4; nt++) {
                int cp = cpb + ((wn * 32 + nt * 8 + 2 * (lane & 3)) >> 1);
                uint32_t h0, l0, h1, l1;
                cvt2(acc[mt][nt][0], acc[mt][nt][1], h0, l0);
                cvt2(acc[mt][nt][2], acc[mt][nt][3], h1, l1);
                size_t a0 = (vb + t) * 256 + cp;
                g_v_hi[a0] = h0; g_v_lo[a0] = l0;
                size_t a1 = a0 + 8 * 256;
                g_v_hi[a1] = h1; g_v_lo[a1] = l1;
            }
        }
    } else {
        // q/k: channel-major token-pairs via smem transpose + norms
        float* sT = (float*)ab;   // 64 x 136
#pragma unroll
        for (int p = 0; p < 2; p++) {
            if ((wn >> 1) == p) {
                int mbase = wm * 64 + (lane >> 2);
                int nbase = (wn & 1) * 32 + 2 * (lane & 3);
#pragma unroll
                for (int mt = 0; mt < 4; mt++)
#pragma unroll
                    for (int nt = 0; nt < 4; nt++) {
                        int m = mbase + mt * 16;
                        int nl = nbase + nt * 8;
                        sT[nl * 136 + m]           = acc[mt][nt][0];
                        sT[(nl + 1) * 136 + m]     = acc[mt][nt][1];
                        sT[nl * 136 + m + 8]       = acc[mt][nt][2];
                        sT[(nl + 1) * 136 + m + 8] = acc[mt][nt][3];
                    }
            }
            __syncthreads();
#pragma unroll
            for (int it = 0; it < 8; it++) {
                int idx = tid + it * 256;
                int nrow = idx >> 5;            // = wid + it*8 (warp-uniform)
                int m4 = (idx & 31) * 4;        // = lane*4
                float4 vv = *(float4*)&sT[nrow * 136 + m4];
                int c = c0 + p * 64 + nrow;
                int rem = c & 511;
                uint32_t h0, l0, h1, l1;
                cvt2(vv.x, vv.y, h0, l0);
                cvt2(vv.z, vv.w, h1, l1);
                size_t rowb = ((size_t)((s * 2 + which) * 8 + b) * 512 + rem) * 2048;
                *(uint2*)&g_qk_hi[rowb + ((n0 + m4) >> 1)] = make_uint2(h0, h1);
                *(uint2*)&g_qk_lo[rowb + ((n0 + m4) >> 1)] = make_uint2(l0, l1);
                float r2 = vv.x * vv.x + vv.y * vv.y + vv.z * vv.z + vv.w * vv.w;
                r2 += __shfl_xor_sync(0xFFFFFFFFu, r2, 16);
                r2 += __shfl_xor_sync(0xFFFFFFFFu, r2, 8);
                r2 += __shfl_xor_sync(0xFFFFFFFFu, r2, 4);
                r2 += __shfl_xor_sync(0xFFFFFFFFu, r2, 2);
                r2 += __shfl_xor_sync(0xFFFFFFFFu, r2, 1);
                if (lane == 0)
                    g_nrm[(((size_t)(s * 2 + which) * 8 + b) * 512 + rem) * 32 + (n0 >> 7)] = r2;
            }
            __syncthreads();
        }
    }
}

// ---------------------------------------------------------------------------
// Kernel 2a: Gram partials via HMMA. grid (chunk 8, bh 64, s 2).
// ---------------------------------------------------------------------------
__global__ __launch_bounds__(256) void attn_gram_kernel()
{
    extern __shared__ char dsm[];
    uint32_t sbr = smem_u32(dsm);
    uint32_t sb = (sbr + 1023) & ~1023u;

    const int tid = threadIdx.x;
    const int wid = tid >> 5;
    const int lane = tid & 31;
    const int wm = wid & 1, wn = wid >> 1;
    const int chunk = blockIdx.x;
    const int bh = blockIdx.y;
    const int s = blockIdx.z;
    const int b = bh >> 3, h = bh & 7;
    const int so = s ^ 1;
    const int g = s * 64 + bh;

    const size_t qrow = ((size_t)(s  * 2 + 0) * 8 + b) * 512 + h * 64;
    const size_t krow = ((size_t)(so * 2 + 1) * 8 + b) * 512 + h * 64;

    float acc[2][2][4];
#pragma unroll
    for (int i = 0; i < 2; i++)
#pragma unroll
        for (int j = 0; j < 2; j++)
#pragma unroll
            for (int r = 0; r < 4; r++) acc[i][j][r] = 0.f;

    const int aRow  = wm * 32 + (lane & 15);
    const int aColb = (lane >> 4) * 16;
    const int bRow  = wn * 16 + (lane & 7) + ((lane >> 4) & 1) * 8;
    const int bColb = ((lane >> 3) & 1) * 16;

    for (int sub = 0; sub < 8; sub++) {
        const int kp0 = chunk * 256 + sub * 32;
#pragma unroll
        for (int it = 0; it < 2; it++) {
            int idx = tid + it * 256;
            int r = idx >> 3, c16 = idx & 7;
            uint32_t dsw = swz((uint32_t)(r * 128 + c16 * 16));
            size_t qa = (qrow + r) * 2048 + kp0 + c16 * 4;
            size_t ka = (krow + r) * 2048 + kp0 + c16 * 4;
            CP_ASYNC16(sb + S1_AHI + dsw, g_qk_hi + qa);
            CP_ASYNC16(sb + S1_ALO + dsw, g_qk_lo + qa);
            CP_ASYNC16(sb + S1_BHI + dsw, g_qk_hi + ka);
            CP_ASYNC16(sb + S1_BLO + dsw, g_qk_lo + ka);
        }
        CP_COMMIT();
        CP_WAIT0();
        __syncthreads();
#pragma unroll
        for (int kk = 0; kk < 4; kk++) {
            uint32_t a[2][4], al[2][4], bhf[2][2], blf[2][2];
#pragma unroll
            for (int mt = 0; mt < 2; mt++) {
                ldmx4(a[mt][0], a[mt][1], a[mt][2], a[mt][3],
                      sb + S1_AHI + swz((uint32_t)((aRow + mt * 16) * 128 + aColb + kk * 32)));
                ldmx4(al[mt][0], al[mt][1], al[mt][2], al[mt][3],
                      sb + S1_ALO + swz((uint32_t)((aRow + mt * 16) * 128 + aColb + kk * 32)));
            }
            ldmx4(bhf[0][0], bhf[0][1], bhf[1][0], bhf[1][1],
                  sb + S1_BHI + swz((uint32_t)(bRow * 128 + bColb + kk * 32)));
            ldmx4(blf[0][0], blf[0][1], blf[1][0], blf[1][1],
                  sb + S1_BLO + swz((uint32_t)(bRow * 128 + bColb + kk * 32)));
#pragma unroll
            for (int mt = 0; mt < 2; mt++)
#pragma unroll
                for (int nt = 0; nt < 2; nt++) {
                    mma16816(acc[mt][nt], a[mt], bhf[nt]);
                    mma16816(acc[mt][nt], a[mt], blf[nt]);
                    mma16816(acc[mt][nt], al[mt], bhf[nt]);
                }
        }
        __syncthreads();
    }

    const size_t base = (size_t)(g * 8 + chunk) * 4096;
#pragma unroll
    for (int mt = 0; mt < 2; mt++)
#pragma unroll
        for (int nt = 0; nt < 2; nt++) {
            int m = wm * 32 + mt * 16 + (lane >> 2);
            int col = wn * 16 + nt * 8 + 2 * (lane & 3);
            *(float2*)&g_pgram[base + m * 64 + col] = make_float2(acc[mt][nt][0], acc[mt][nt][1]);
            *(float2*)&g_pgram[base + (m + 8) * 64 + col] = make_float2(acc[mt][nt][2], acc[mt][nt][3]);
        }
}

// ---------------------------------------------------------------------------
// Kernel 2b: reduce partials + norms, softmax, emit P hi/lo
// ---------------------------------------------------------------------------
__global__ __launch_bounds__(256) void attn_softmax_kernel(
    const float* __restrict__ temp_rgb, const float* __restrict__ temp_T)
{
    const int g = blockIdx.x;
    const int s = g >> 6;
    const int bh = g & 63;
    const int b = bh >> 3, h = bh & 7;
    const int so = s ^ 1;
    const float temp = (s ? temp_T : temp_rgb)[h];

    __shared__ float sP[64 * 65];
    __shared__ float qn[64], kn[64];
    const int tid = threadIdx.x;

#pragma unroll
    for (int it = 0; it < 16; it++) {
        int idx = tid + it * 256;
        int i = idx >> 6, j = idx & 63;
        float sum = 0.f;
#pragma unroll
        for (int c = 0; c < 8; c++) sum += g_pgram[(size_t)(g * 8 + c) * 4096 + idx];
        sP[i * 65 + j] = sum;
    }
    if (tid < 64) {
        float sq = 0.f;
        size_t nb = (((size_t)(s * 2 + 0) * 8 + b) * 512 + h * 64 + tid) * 32;
#pragma unroll
        for (int t = 0; t < 32; t++) sq += g_nrm[nb + t];
        qn[tid] = sqrtf(sq);
    } else if (tid < 128) {
        float sk = 0.f;
        size_t nb = (((size_t)(so * 2 + 1) * 8 + b) * 512 + h * 64 + tid - 64) * 32;
#pragma unroll
        for (int t = 0; t < 32; t++) sk += g_nrm[nb + t];
        kn[tid - 64] = sqrtf(sk);
    }
    __syncthreads();

    if (tid < 64) {
        const int i = tid;
        const float qi = fmaxf(qn[i], 1e-12f);
        float mx = -1e30f;
        for (int j = 0; j < 64; j++) {
            float val = sP[i * 65 + j] * temp / (qi * fmaxf(kn[j], 1e-12f));
            sP[i * 65 + j] = val;
            mx = fmaxf(mx, val);
        }
        float sum = 0.f;
        for (int j = 0; j < 64; j++) {
            float e = __expf(sP[i * 65 + j] - mx);
            sP[i * 65 + j] = e;
            sum += e;
        }
        float inv = 1.f / sum;
        for (int j = 0; j < 64; j++) sP[i * 65 + j] *= inv;
    }
    __syncthreads();

#pragma unroll
    for (int it = 0; it < 8; it++) {
        int idx = tid + it * 256;           // d*32 + ep
        int d = idx >> 5, ep = idx & 31;
        uint32_t hi, lo;
        cvt2(sP[d * 65 + 2 * ep], sP[d * 65 + 2 * ep + 1], hi, lo);
        g_p_hi[(size_t)g * 2048 + idx] = hi;
        g_p_lo[(size_t)g * 2048 + idx] = lo;
    }
}

// ---------------------------------------------------------------------------
// Kernel 2c: out = P @ v via HMMA. grid (tile 32, bh 64, s 2).
// C[token 128][d 64], K = e 64.  A=v token-major, B=P.
// ---------------------------------------------------------------------------
__global__ __launch_bounds__(256) void attn_pv_kernel()
{
    extern __shared__ char dsm[];
    uint32_t sbr = smem_u32(dsm);
    uint32_t sb = (sbr + 1023) & ~1023u;

    const int tid = threadIdx.x;
    const int wid = tid >> 5;
    const int lane = tid & 31;
    const int wm = wid & 1, wn = wid >> 1;
    const int n0 = blockIdx.x * 128;
    const int bh = blockIdx.y;
    const int s = blockIdx.z;
    const int b = bh >> 3, h = bh & 7;
    const int so = s ^ 1;
    const int g = s * 64 + bh;
    const size_t vb = (size_t)(so * 8 + b) * 4096;   // v from opposite stream

#pragma unroll
    for (int it = 0; it < 4; it++) {
        int idx = tid + it * 256;
        int r = idx >> 3, c16 = idx & 7;
        uint32_t dsw = swz((uint32_t)(r * 128 + c16 * 16));
        size_t va = (vb + n0 + r) * 256 + h * 32 + c16 * 4;
        CP_ASYNC16(sb + S2_AHI + dsw, g_v_hi + va);
        CP_ASYNC16(sb + S2_ALO + dsw, g_v_lo + va);
    }
#pragma unroll
    for (int it = 0; it < 2; it++) {
        int idx = tid + it * 256;
        int r = idx >> 3, c16 = idx & 7;
        uint32_t dsw = swz((uint32_t)(r * 128 + c16 * 16));
        size_t pa = (size_t)g * 2048 + r * 32 + c16 * 4;
        CP_ASYNC16(sb + S2_BHI + dsw, g_p_hi + pa);
        CP_ASYNC16(sb + S2_BLO + dsw, g_p_lo + pa);
    }
    CP_COMMIT();
    CP_WAIT0();
    __syncthreads();

    float acc[4][2][4];
#pragma unroll
    for (int i = 0; i < 4; i++)
#pragma unroll
        for (int j = 0; j < 2; j++)
#pragma unroll
            for (int r = 0; r < 4; r++) acc[i][j][r] = 0.f;

    const int aRow  = wm * 64 + (lane & 15);
    const int aColb = (lane >> 4) * 16;
    const int bRow  = wn * 16 + (lane & 7) + ((lane >> 4) & 1) * 8;
    const int bColb = ((lane >> 3) & 1) * 16;

#pragma unroll
    for (int kk = 0; kk < 4; kk++) {
        uint32_t a[4][4], al[4][4], bhf[2][2], blf[2][2];
#pragma unroll
        for (int mt = 0; mt < 4; mt++) {
            ldmx4(a[mt][0], a[mt][1], a[mt][2], a[mt][3],
                  sb + S2_AHI + swz((uint32_t)((aRow + mt * 16) * 128 + aColb + kk * 32)));
            ldmx4(al[mt][0], al[mt][1], al[mt][2], al[mt][3],
                  sb + S2_ALO + swz((uint32_t)((aRow + mt * 16) * 128 + aColb + kk * 32)));
        }
        ldmx4(bhf[0][0], bhf[0][1], bhf[1][0], bhf[1][1],
              sb + S2_BHI + swz((uint32_t)(bRow * 128 + bColb + kk * 32)));
        ldmx4(blf[0][0], blf[0][1], blf[1][0], blf[1][1],
              sb + S2_BLO + swz((uint32_t)(bRow * 128 + bColb + kk * 32)));
#pragma unroll
        for (int mt = 0; mt < 4; mt++)
#pragma unroll
            for (int nt = 0; nt < 2; nt++) {
                mma16816(acc[mt][nt], a[mt], bhf[nt]);
                mma16816(acc[mt][nt], a[mt], blf[nt]);
                mma16816(acc[mt][nt], al[mt], bhf[nt]);
            }
    }

    // pack d-pairs directly from frags -> att token-major [n][kpair]
    const size_t ob = (size_t)(s * 8 + b) * 4096;
#pragma unroll
    for (int mt = 0; mt < 4; mt++) {
        int t = n0 + wm * 64 + mt * 16 + (lane >> 2);
#pragma unroll
        for (int nt = 0; nt < 2; nt++) {
            int dp = wn * 8 + nt * 4 + (lane & 3);
            uint32_t h0, l0, h1, l1;
            cvt2(acc[mt][nt][0], acc[mt][nt][1], h0, l0);
            cvt2(acc[mt][nt][2], acc[mt][nt][3], h1, l1);
            size_t a0 = (ob + t) * 256 + h * 32 + dp;
            g_att_hi[a0] = h0; g_att_lo[a0] = l0;
            size_t a1 = a0 + 8 * 256;
            g_att_hi[a1] = h1; g_att_lo[a1] = l1;
        }
    }
}

// ---------------------------------------------------------------------------
// Kernel 3: proj GEMM.  out[token][channel] = att @ W + b.
// ---------------------------------------------------------------------------
__global__ __launch_bounds__(256, 2) void proj_mma_kernel(
    const float* __restrict__ br, const float* __restrict__ bt,
    float* __restrict__ out)
{
    extern __shared__ char dsm[];
    uint32_t sbr = smem_u32(dsm);
    uint32_t sb = (sbr + 1023) & ~1023u;
    char* ab = dsm + (sb - sbr);

    const int tid = threadIdx.x;
    const int wid = tid >> 5;
    const int lane = tid & 31;
    const int wm = wid & 1, wn = wid >> 1;
    const int z = blockIdx.z;
    const int s = z >> 3, b = z & 7;
    const float* __restrict__ bias = s ? bt : br;
    const int n0 = blockIdx.x * 128;
    const int c0 = blockIdx.y * 128;

    const size_t aBase = (((size_t)(s * 8 + b)) * 4096 + n0) * 256;
    const size_t bBase = ((size_t)s * 512 + c0) * 256;

    float acc[4][4][4];
#pragma unroll
    for (int i = 0; i < 4; i++)
#pragma unroll
        for (int j = 0; j < 4; j++)
#pragma unroll
            for (int r = 0; r < 4; r++) acc[i][j][r] = 0.f;

    for (int chunk = 0; chunk < 8; chunk++) {
        fill_chunk(sb, tid, chunk * 32, g_att_hi, g_att_lo, aBase, g_wp_hi, g_wp_lo, bBase);
        CP_WAIT0();
        __syncthreads();
        mma_chunk(sb, wm, wn, lane, acc);
        __syncthreads();
    }

    float* sT = (float*)ab;   // 64 x 136
    float* outp = out + (size_t)(s * 8 + b) * 2097152;
#pragma unroll
    for (int p = 0; p < 2; p++) {
        if (wm == p) {
            int mbase = (lane >> 2);
            int nbase = wn * 32 + 2 * (lane & 3);
#pragma unroll
            for (int mt = 0; mt < 4; mt++)
#pragma unroll
                for (int nt = 0; nt < 4; nt++) {
                    int m = mbase + mt * 16;
                    int nc = nbase + nt * 8;
                    sT[m * 136 + nc]           = acc[mt][nt][0];
                    sT[m * 136 + nc + 1]       = acc[mt][nt][1];
                    sT[(m + 8) * 136 + nc]     = acc[mt][nt][2];
                    sT[(m + 8) * 136 + nc + 1] = acc[mt][nt][3];
                }
        }
        __syncthreads();
#pragma unroll
        for (int it = 0; it < 8; it++) {
            int idx = tid + it * 256;
            int mrow = idx >> 5, ch4 = (idx & 31) * 4;
            int tok = n0 + p * 64 + mrow;
            float4 vv = *(float4*)&sT[mrow * 136 + ch4];
            float4 bb = *(const float4*)&bias[c0 + ch4];
            vv.x += bb.x; vv.y += bb.y; vv.z += bb.z; vv.w += bb.w;
            *(float4*)&outp[(size_t)tok * 512 + c0 + ch4] = vv;
        }
        __syncthreads();
    }
}

// ---------------------------------------------------------------------------
extern "C" void kernel_launch(void* const* d_in, const int* in_sizes, int n_in,
                              void* d_out, int out_size)
{
    const float* x        = (const float*)d_in[0];
    const float* x_d      = (const float*)d_in[1];
    const float* W_qkv_r  = (const float*)d_in[2];
    const float* W_qkv_T  = (const float*)d_in[3];
    const float* temp_r   = (const float*)d_in[4];
    const float* temp_T   = (const float*)d_in[5];
    const float* W_proj_r = (const float*)d_in[6];
    const float* b_proj_r = (const float*)d_in[7];
    const float* W_proj_T = (const float*)d_in[8];
    const float* b_proj_T = (const float*)d_in[9];
    float* out = (float*)d_out;

    cudaFuncSetAttribute(qkv_mma_kernel,
        cudaFuncAttributeMaxDynamicSharedMemorySize, GEMM_SMEM_BYTES);
    cudaFuncSetAttribute(proj_mma_kernel,
        cudaFuncAttributeMaxDynamicSharedMemorySize, GEMM_SMEM_BYTES);
    cudaFuncSetAttribute(attn_pv_kernel,
        cudaFuncAttributeMaxDynamicSharedMemorySize, PV_SMEM_BYTES);

    prep_x_kernel<<<65536, 256>>>(x, x_d);
    prep_w_kernel<<<4096, 256>>>(W_qkv_r, W_qkv_T, W_proj_r, W_proj_T);

    {
        dim3 grid(256, 12, 2);
        qkv_mma_kernel<<<grid, 256, GEMM_SMEM_BYTES>>>();
    }
    {
        dim3 g1(8, 64, 2);
        attn_gram_kernel<<<g1, 256, GRAM_SMEM_BYTES>>>();
        attn_softmax_kernel<<<128, 256>>>(temp_r, temp_T);
        dim3 g2(32, 64, 2);
        attn_pv_kernel<<<g2, 256, PV_SMEM_BYTES>>>();
    }
    {
        dim3 grid(32, 4, 16);
        proj_mma_kernel<<<grid, 256, GEMM_SMEM_BYTES>>>(b_proj_r, b_proj_T, out);
    }
}

// round 8
// speedup vs baseline: 3.6753x; 1.2545x over previous
#include <cuda_runtime.h>
#include <cuda_fp16.h>
#include <math.h>
#include <stdint.h>

// ---------------------------------------------------------------------------
// ChannelCrossAttention — HMMA fp16 2-term split (A = hi+lo fp16 exact,
// B = single fp16). 128x256 CTA tiles, 64x64 warp tiles, double-buffered
// cp.async pipeline, L2-friendly grid order.
// ---------------------------------------------------------------------------

// packed 2xfp16 per u32 everywhere
__device__ uint32_t g_x_h[2u * 32768u * 256u];     // [s][m][kpair]
__device__ uint32_t g_x_l[2u * 32768u * 256u];
__device__ uint32_t g_wq_h[2u * 1536u * 256u];     // [s][c][kpair]
__device__ uint32_t g_wp_h[2u * 512u * 256u];
// q,k channel-major: [s][w(q=0,k=1)][b][c 512][tokenpair 2048]
__device__ uint32_t g_qk_h[2u * 2u * 8u * 512u * 2048u];
__device__ uint32_t g_qk_l[2u * 2u * 8u * 512u * 2048u];   // only q uses lo
// v token-major: [s][b][n 4096][cpair 256]
__device__ uint32_t g_v_h[2u * 8u * 4096u * 256u];
__device__ uint32_t g_v_l[2u * 8u * 4096u * 256u];
// attention out token-major: [s][b][n][kpair 256]
__device__ uint32_t g_att_h[2u * 8u * 4096u * 256u];
__device__ uint32_t g_att_l[2u * 8u * 4096u * 256u];
// per-channel sumsq partials: [s][w][b][c 512][mtile 32]
__device__ float g_nrm[2u * 2u * 8u * 512u * 32u];
// Gram partials [g 128][chunk 8][64*64]
__device__ float g_pgram[128u * 8u * 4096u];
// P packed fp16 [g][d 64][epair 32]
__device__ uint32_t g_p_h[128u * 2048u];

// ---------------------------------------------------------------------------
__device__ __forceinline__ uint32_t smem_u32(const void* p) {
    uint32_t a;
    asm("{ .reg .u64 t; cvta.to.shared.u64 t, %1; cvt.u32.u64 %0, t; }" : "=r"(a) : "l"(p));
    return a;
}
__device__ __forceinline__ uint32_t swz(uint32_t off) { return off ^ ((off >> 3) & 0x70); }

__device__ __forceinline__ void ldmx4(uint32_t& r0, uint32_t& r1, uint32_t& r2, uint32_t& r3,
                                      uint32_t addr) {
    asm volatile("ldmatrix.sync.aligned.m8n8.x4.shared.b16 {%0,%1,%2,%3}, [%4];"
        : "=r"(r0), "=r"(r1), "=r"(r2), "=r"(r3) : "r"(addr));
}
__device__ __forceinline__ void mma_h(float* c, const uint32_t* a, const uint32_t* b) {
    asm volatile("mma.sync.aligned.m16n8k16.row.col.f32.f16.f16.f32 "
        "{%0,%1,%2,%3}, {%4,%5,%6,%7}, {%8,%9}, {%0,%1,%2,%3};"
        : "+f"(c[0]), "+f"(c[1]), "+f"(c[2]), "+f"(c[3])
        : "r"(a[0]), "r"(a[1]), "r"(a[2]), "r"(a[3]), "r"(b[0]), "r"(b[1]));
}
#define CP_ASYNC16(dst, src) \
    asm volatile("cp.async.cg.shared.global [%0], [%1], 16;" :: "r"(dst), "l"(src))
#define CP_COMMIT() asm volatile("cp.async.commit_group;")
#define CP_WAIT0()  asm volatile("cp.async.wait_group 0;")
#define CP_WAIT1()  asm volatile("cp.async.wait_group 1;")

__device__ __forceinline__ uint32_t packh(__half a, __half b) {
    return (uint32_t)__half_as_ushort(a) | ((uint32_t)__half_as_ushort(b) << 16);
}
__device__ __forceinline__ void cvt2h(float a, float b, uint32_t& hi, uint32_t& lo) {
    __half ha = __float2half_rn(a), hb = __float2half_rn(b);
    __half la = __float2half_rn(a - __half2float(ha));
    __half lb = __float2half_rn(b - __half2float(hb));
    hi = packh(ha, hb);
    lo = packh(la, lb);
}
__device__ __forceinline__ uint32_t cvt1h(float a, float b) {
    return packh(__float2half_rn(a), __float2half_rn(b));
}

// qkv/proj smem: stage = A-hi 16K | A-lo 16K | B 32K = 64KB, 2 stages
#define SQ_AHI(st) ((st) * 65536 + 0)
#define SQ_ALO(st) ((st) * 65536 + 16384)
#define SQ_B(st)   ((st) * 65536 + 32768)
#define QKV_SMEM (131072 + 1024)
// gram smem: stage = q-hi 8K | q-lo 8K | k-hi 8K = 24KB, 2 stages
#define SG_QH(st) ((st) * 24576 + 0)
#define SG_QL(st) ((st) * 24576 + 8192)
#define SG_KH(st) ((st) * 24576 + 16384)
#define GRAM_SMEM (49152 + 1024)
// pv smem: v-hi 16K | v-lo 16K | P 8K
#define SP_VH 0
#define SP_VL 16384
#define SP_P  32768
#define PV_SMEM (40960 + 1024)

// ---------------------------------------------------------------------------
// Prep kernels
// ---------------------------------------------------------------------------
__global__ __launch_bounds__(256) void prep_x_kernel(
    const float* __restrict__ x, const float* __restrict__ x_d)
{
    int idx = blockIdx.x * 256 + threadIdx.x;
    int s = idx >> 23;
    int r = idx & 0x7FFFFF;
    int m = r >> 8, kp = r & 255;
    const float* X = s ? x_d : x;
    float2 v = *(const float2*)&X[(size_t)m * 512 + kp * 2];
    uint32_t hi, lo; cvt2h(v.x, v.y, hi, lo);
    g_x_h[idx] = hi; g_x_l[idx] = lo;
}

__global__ __launch_bounds__(256) void prep_w_kernel(
    const float* __restrict__ Wq_r, const float* __restrict__ Wq_T,
    const float* __restrict__ Wp_r, const float* __restrict__ Wp_T)
{
    int idx = blockIdx.x * 256 + threadIdx.x;
    const int TQ = 2 * 1536 * 256;
    const int TP = 2 * 512 * 256;
    if (idx < TQ) {
        int s = idx / (1536 * 256);
        int r = idx % (1536 * 256);
        int c = r >> 8, kp = r & 255;
        const float* W = s ? Wq_T : Wq_r;
        g_wq_h[idx] = cvt1h(W[(size_t)(2 * kp) * 1536 + c],
                            W[(size_t)(2 * kp + 1) * 1536 + c]);
    } else if (idx < TQ + TP) {
        int i2 = idx - TQ;
        int s = i2 / (512 * 256);
        int r = i2 % (512 * 256);
        int c = r >> 8, kp = r & 255;
        const float* W = s ? Wp_T : Wp_r;
        g_wp_h[i2] = cvt1h(W[(size_t)(2 * kp) * 512 + c],
                           W[(size_t)(2 * kp + 1) * 512 + c]);
    }
}

// ---------------------------------------------------------------------------
// Big-tile GEMM core: CTA 128(m) x 256(n), warp 64x64 (wm 2 x wn 4).
// ---------------------------------------------------------------------------
__device__ __forceinline__ void fill_big(uint32_t sb, int st, int tid, int kp0,
    const uint32_t* __restrict__ AH, const uint32_t* __restrict__ AL, size_t aBase,
    const uint32_t* __restrict__ B, size_t bBase)
{
#pragma unroll
    for (int it = 0; it < 4; it++) {
        int idx = tid + it * 256;          // 1024 lines per A region
        int r = idx >> 3, c16 = idx & 7;
        uint32_t dsw = swz((uint32_t)(r * 128 + c16 * 16));
        size_t so = aBase + (size_t)r * 256 + kp0 + c16 * 4;
        CP_ASYNC16(sb + SQ_AHI(st) + dsw, AH + so);
        CP_ASYNC16(sb + SQ_ALO(st) + dsw, AL + so);
    }
#pragma unroll
    for (int it = 0; it < 8; it++) {
        int idx = tid + it * 256;          // 2048 lines for B
        int r = idx >> 3, c16 = idx & 7;
        uint32_t dsw = swz((uint32_t)(r * 128 + c16 * 16));
        CP_ASYNC16(sb + SQ_B(st) + dsw, B + bBase + (size_t)r * 256 + kp0 + c16 * 4);
    }
    CP_COMMIT();
}

__device__ __forceinline__ void mma_big(uint32_t sb, int st, int wm, int wn, int lane,
                                        float acc[4][8][4])
{
    const int aRow  = wm * 64 + (lane & 15);
    const int aColb = (lane >> 4) * 16;
    const int bRow  = wn * 64 + (lane & 7) + ((lane >> 4) & 1) * 8;
    const int bColb = ((lane >> 3) & 1) * 16;
#pragma unroll
    for (int kk = 0; kk < 4; kk++) {
        uint32_t ah[4][4], al[4][4], bf[8][2];
#pragma unroll
        for (int mt = 0; mt < 4; mt++) {
            ldmx4(ah[mt][0], ah[mt][1], ah[mt][2], ah[mt][3],
                  sb + SQ_AHI(st) + swz((uint32_t)((aRow + mt * 16) * 128 + aColb + kk * 32)));
            ldmx4(al[mt][0], al[mt][1], al[mt][2], al[mt][3],
                  sb + SQ_ALO(st) + swz((uint32_t)((aRow + mt * 16) * 128 + aColb + kk * 32)));
        }
#pragma unroll
        for (int j = 0; j < 4; j++)
            ldmx4(bf[2 * j][0], bf[2 * j][1], bf[2 * j + 1][0], bf[2 * j + 1][1],
                  sb + SQ_B(st) + swz((uint32_t)((bRow + j * 16) * 128 + bColb + kk * 32)));
#pragma unroll
        for (int mt = 0; mt < 4; mt++)
#pragma unroll
            for (int nj = 0; nj < 8; nj++) {
                mma_h(acc[mt][nj], ah[mt], bf[nj]);
                mma_h(acc[mt][nj], al[mt], bf[nj]);
            }
    }
}

// ---------------------------------------------------------------------------
// Kernel 1: qkv GEMM.  grid (cTile 6, mTile 256, s 2)
// ---------------------------------------------------------------------------
__global__ __launch_bounds__(256, 1) void qkv_mma_kernel()
{
    extern __shared__ char dsm[];
    uint32_t sbr = smem_u32(dsm);
    uint32_t sb = (sbr + 1023) & ~1023u;
    char* ab = dsm + (sb - sbr);

    const int tid = threadIdx.x;
    const int wid = tid >> 5;
    const int lane = tid & 31;
    const int wm = wid & 1, wn = wid >> 1;
    const int s = blockIdx.z;
    const int m0 = blockIdx.y * 128;
    const int c0 = blockIdx.x * 256;
    const int b = m0 >> 12, n0 = m0 & 4095;
    const int which = c0 >> 9;          // 0=q 1=k 2=v

    const size_t aBase = ((size_t)s * 32768 + m0) * 256;
    const size_t bBase = ((size_t)s * 1536 + c0) * 256;

    float acc[4][8][4];
#pragma unroll
    for (int i = 0; i < 4; i++)
#pragma unroll
        for (int j = 0; j < 8; j++)
#pragma unroll
            for (int r = 0; r < 4; r++) acc[i][j][r] = 0.f;

    fill_big(sb, 0, tid, 0, g_x_h, g_x_l, aBase, g_wq_h, bBase);
    for (int c = 0; c < 8; c++) {
        int st = c & 1;
        if (c < 7) fill_big(sb, st ^ 1, tid, (c + 1) * 32, g_x_h, g_x_l, aBase, g_wq_h, bBase);
        if (c < 7) CP_WAIT1(); else CP_WAIT0();
        __syncthreads();
        mma_big(sb, st, wm, wn, lane, acc);
        __syncthreads();
    }

    if (which == 2) {
        // v: pack channel-pairs from frags -> token-major [n][cpair]
        const size_t vb = (size_t)(s * 8 + b) * 4096;
        const int cb = c0 - 1024;
#pragma unroll
        for (int mt = 0; mt < 4; mt++) {
            int t = n0 + wm * 64 + mt * 16 + (lane >> 2);
#pragma unroll
            for (int nj = 0; nj < 8; nj++) {
                int cp = (cb + wn * 64 + nj * 8 + 2 * (lane & 3)) >> 1;
                uint32_t h0, l0, h1, l1;
                cvt2h(acc[mt][nj][0], acc[mt][nj][1], h0, l0);
                cvt2h(acc[mt][nj][2], acc[mt][nj][3], h1, l1);
                size_t a0 = (vb + t) * 256 + cp;
                g_v_h[a0] = h0; g_v_l[a0] = l0;
                size_t a1 = a0 + 8 * 256;
                g_v_h[a1] = h1; g_v_l[a1] = l1;
            }
        }
    } else {
        // q/k: channel-major token-pairs via smem transpose + exact norms
        float* sT = (float*)ab;   // 64 x 136 fp32
#pragma unroll
        for (int p = 0; p < 4; p++) {
            if (wn == p) {
#pragma unroll
                for (int mt = 0; mt < 4; mt++)
#pragma unroll
                    for (int nj = 0; nj < 8; nj++) {
                        int m = wm * 64 + mt * 16 + (lane >> 2);
                        int cl = nj * 8 + 2 * (lane & 3);
                        sT[cl * 136 + m]           = acc[mt][nj][0];
                        sT[(cl + 1) * 136 + m]     = acc[mt][nj][1];
                        sT[cl * 136 + m + 8]       = acc[mt][nj][2];
                        sT[(cl + 1) * 136 + m + 8] = acc[mt][nj][3];
                    }
            }
            __syncthreads();
#pragma unroll
            for (int it = 0; it < 8; it++) {
                int idx = tid + it * 256;
                int row = idx >> 5;            // 0..63 (warp-uniform)
                int m4 = (idx & 31) * 4;       // lane*4
                float4 vv = *(float4*)&sT[row * 136 + m4];
                int c = c0 + p * 64 + row;
                int rem = c & 511;
                uint32_t h0, l0, h1, l1;
                cvt2h(vv.x, vv.y, h0, l0);
                cvt2h(vv.z, vv.w, h1, l1);
                size_t rowb = ((size_t)((s * 2 + which) * 8 + b) * 512 + rem) * 2048;
                *(uint2*)&g_qk_h[rowb + ((n0 + m4) >> 1)] = make_uint2(h0, h1);
                if (which == 0)
                    *(uint2*)&g_qk_l[rowb + ((n0 + m4) >> 1)] = make_uint2(l0, l1);
                float r2 = vv.x * vv.x + vv.y * vv.y + vv.z * vv.z + vv.w * vv.w;
                r2 += __shfl_xor_sync(0xFFFFFFFFu, r2, 16);
                r2 += __shfl_xor_sync(0xFFFFFFFFu, r2, 8);
                r2 += __shfl_xor_sync(0xFFFFFFFFu, r2, 4);
                r2 += __shfl_xor_sync(0xFFFFFFFFu, r2, 2);
                r2 += __shfl_xor_sync(0xFFFFFFFFu, r2, 1);
                if (lane == 0)
                    g_nrm[(((size_t)(s * 2 + which) * 8 + b) * 512 + rem) * 32 + (n0 >> 7)] = r2;
            }
            __syncthreads();
        }
    }
}

// ---------------------------------------------------------------------------
// Kernel 2a: Gram partials (2-term fp16), double-buffered.
// grid (chunk 8, bh 64, s 2)
// ---------------------------------------------------------------------------
__global__ __launch_bounds__(256) void attn_gram_kernel()
{
    extern __shared__ char dsm[];
    uint32_t sbr = smem_u32(dsm);
    uint32_t sb = (sbr + 1023) & ~1023u;

    const int tid = threadIdx.x;
    const int wid = tid >> 5;
    const int lane = tid & 31;
    const int wm = wid & 1, wn = wid >> 1;
    const int chunk = blockIdx.x;
    const int bh = blockIdx.y;
    const int s = blockIdx.z;
    const int b = bh >> 3, h = bh & 7;
    const int so = s ^ 1;
    const int g = s * 64 + bh;

    const size_t qrow = ((size_t)(s  * 2 + 0) * 8 + b) * 512 + h * 64;
    const size_t krow = ((size_t)(so * 2 + 1) * 8 + b) * 512 + h * 64;

    float acc[2][2][4];
#pragma unroll
    for (int i = 0; i < 2; i++)
#pragma unroll
        for (int j = 0; j < 2; j++)
#pragma unroll
            for (int r = 0; r < 4; r++) acc[i][j][r] = 0.f;

    const int aRow  = wm * 32 + (lane & 15);
    const int aColb = (lane >> 4) * 16;
    const int bRow  = wn * 16 + (lane & 7) + ((lane >> 4) & 1) * 8;
    const int bColb = ((lane >> 3) & 1) * 16;

    // fill helper inlined: sub s -> token-pair offset
    auto fill_sub = [&](int st, int sub) {
        int tp0 = chunk * 256 + sub * 32;
#pragma unroll
        for (int it = 0; it < 2; it++) {
            int idx = tid + it * 256;
            int r = idx >> 3, c16 = idx & 7;
            uint32_t dsw = swz((uint32_t)(r * 128 + c16 * 16));
            size_t qa = (qrow + r) * 2048 + tp0 + c16 * 4;
            size_t ka = (krow + r) * 2048 + tp0 + c16 * 4;
            CP_ASYNC16(sb + SG_QH(st) + dsw, g_qk_h + qa);
            CP_ASYNC16(sb + SG_QL(st) + dsw, g_qk_l + qa);
            CP_ASYNC16(sb + SG_KH(st) + dsw, g_qk_h + ka);
        }
        CP_COMMIT();
    };

    fill_sub(0, 0);
    for (int sub = 0; sub < 8; sub++) {
        int st = sub & 1;
        if (sub < 7) fill_sub(st ^ 1, sub + 1);
        if (sub < 7) CP_WAIT1(); else CP_WAIT0();
        __syncthreads();
#pragma unroll
        for (int kk = 0; kk < 4; kk++) {
            uint32_t qh[2][4], ql[2][4], kf[2][2];
#pragma unroll
            for (int mt = 0; mt < 2; mt++) {
                ldmx4(qh[mt][0], qh[mt][1], qh[mt][2], qh[mt][3],
                      sb + SG_QH(st) + swz((uint32_t)((aRow + mt * 16) * 128 + aColb + kk * 32)));
                ldmx4(ql[mt][0], ql[mt][1], ql[mt][2], ql[mt][3],
                      sb + SG_QL(st) + swz((uint32_t)((aRow + mt * 16) * 128 + aColb + kk * 32)));
            }
            ldmx4(kf[0][0], kf[0][1], kf[1][0], kf[1][1],
                  sb + SG_KH(st) + swz((uint32_t)(bRow * 128 + bColb + kk * 32)));
#pragma unroll
            for (int mt = 0; mt < 2; mt++)
#pragma unroll
                for (int nt = 0; nt < 2; nt++) {
                    mma_h(acc[mt][nt], qh[mt], kf[nt]);
                    mma_h(acc[mt][nt], ql[mt], kf[nt]);
                }
        }
        __syncthreads();
    }

    const size_t base = (size_t)(g * 8 + chunk) * 4096;
#pragma unroll
    for (int mt = 0; mt < 2; mt++)
#pragma unroll
        for (int nt = 0; nt < 2; nt++) {
            int m = wm * 32 + mt * 16 + (lane >> 2);
            int col = wn * 16 + nt * 8 + 2 * (lane & 3);
            *(float2*)&g_pgram[base + m * 64 + col] = make_float2(acc[mt][nt][0], acc[mt][nt][1]);
            *(float2*)&g_pgram[base + (m + 8) * 64 + col] = make_float2(acc[mt][nt][2], acc[mt][nt][3]);
        }
}

// ---------------------------------------------------------------------------
// Kernel 2b: reduce partials + norms, softmax, emit P fp16
// ---------------------------------------------------------------------------
__global__ __launch_bounds__(256) void attn_softmax_kernel(
    const float* __restrict__ temp_rgb, const float* __restrict__ temp_T)
{
    const int g = blockIdx.x;
    const int s = g >> 6;
    const int bh = g & 63;
    const int b = bh >> 3, h = bh & 7;
    const int so = s ^ 1;
    const float temp = (s ? temp_T : temp_rgb)[h];

    __shared__ float sP[64 * 65];
    __shared__ float qn[64], kn[64];
    const int tid = threadIdx.x;

#pragma unroll
    for (int it = 0; it < 16; it++) {
        int idx = tid + it * 256;
        int i = idx >> 6, j = idx & 63;
        float sum = 0.f;
#pragma unroll
        for (int c = 0; c < 8; c++) sum += g_pgram[(size_t)(g * 8 + c) * 4096 + idx];
        sP[i * 65 + j] = sum;
    }
    if (tid < 64) {
        float sq = 0.f;
        size_t nb = (((size_t)(s * 2 + 0) * 8 + b) * 512 + h * 64 + tid) * 32;
#pragma unroll
        for (int t = 0; t < 32; t++) sq += g_nrm[nb + t];
        qn[tid] = sqrtf(sq);
    } else if (tid < 128) {
        float sk = 0.f;
        size_t nb = (((size_t)(so * 2 + 1) * 8 + b) * 512 + h * 64 + tid - 64) * 32;
#pragma unroll
        for (int t = 0; t < 32; t++) sk += g_nrm[nb + t];
        kn[tid - 64] = sqrtf(sk);
    }
    __syncthreads();

    if (tid < 64) {
        const int i = tid;
        const float qi = fmaxf(qn[i], 1e-12f);
        float mx = -1e30f;
        for (int j = 0; j < 64; j++) {
            float val = sP[i * 65 + j] * temp / (qi * fmaxf(kn[j], 1e-12f));
            sP[i * 65 + j] = val;
            mx = fmaxf(mx, val);
        }
        float sum = 0.f;
        for (int j = 0; j < 64; j++) {
            float e = __expf(sP[i * 65 + j] - mx);
            sP[i * 65 + j] = e;
            sum += e;
        }
        float inv = 1.f / sum;
        for (int j = 0; j < 64; j++) sP[i * 65 + j] *= inv;
    }
    __syncthreads();

#pragma unroll
    for (int it = 0; it < 8; it++) {
        int idx = tid + it * 256;           // d*32 + ep
        int d = idx >> 5, ep = idx & 31;
        g_p_h[(size_t)g * 2048 + idx] = cvt1h(sP[d * 65 + 2 * ep], sP[d * 65 + 2 * ep + 1]);
    }
}

// ---------------------------------------------------------------------------
// Kernel 2c: out = P @ v (2-term on v, P single). grid (tile 32, bh 64, s 2)
// ---------------------------------------------------------------------------
__global__ __launch_bounds__(256) void attn_pv_kernel()
{
    extern __shared__ char dsm[];
    uint32_t sbr = smem_u32(dsm);
    uint32_t sb = (sbr + 1023) & ~1023u;

    const int tid = threadIdx.x;
    const int wid = tid >> 5;
    const int lane = tid & 31;
    const int wm = wid & 1, wn = wid >> 1;
    const int n0 = blockIdx.x * 128;
    const int bh = blockIdx.y;
    const int s = blockIdx.z;
    const int b = bh >> 3, h = bh & 7;
    const int so = s ^ 1;
    const int g = s * 64 + bh;
    const size_t vb = (size_t)(so * 8 + b) * 4096;

#pragma unroll
    for (int it = 0; it < 4; it++) {
        int idx = tid + it * 256;
        int r = idx >> 3, c16 = idx & 7;
        uint32_t dsw = swz((uint32_t)(r * 128 + c16 * 16));
        size_t va = (vb + n0 + r) * 256 + h * 32 + c16 * 4;
        CP_ASYNC16(sb + SP_VH + dsw, g_v_h + va);
        CP_ASYNC16(sb + SP_VL + dsw, g_v_l + va);
    }
#pragma unroll
    for (int it = 0; it < 2; it++) {
        int idx = tid + it * 256;
        int r = idx >> 3, c16 = idx & 7;
        uint32_t dsw = swz((uint32_t)(r * 128 + c16 * 16));
        CP_ASYNC16(sb + SP_P + dsw, g_p_h + (size_t)g * 2048 + r * 32 + c16 * 4);
    }
    CP_COMMIT();
    CP_WAIT0();
    __syncthreads();

    float acc[4][2][4];
#pragma unroll
    for (int i = 0; i < 4; i++)
#pragma unroll
        for (int j = 0; j < 2; j++)
#pragma unroll
            for (int r = 0; r < 4; r++) acc[i][j][r] = 0.f;

    const int aRow  = wm * 64 + (lane & 15);
    const int aColb = (lane >> 4) * 16;
    const int bRow  = wn * 16 + (lane & 7) + ((lane >> 4) & 1) * 8;
    const int bColb = ((lane >> 3) & 1) * 16;

#pragma unroll
    for (int kk = 0; kk < 4; kk++) {
        uint32_t vh[4][4], vl[4][4], pf[2][2];
#pragma unroll
        for (int mt = 0; mt < 4; mt++) {
            ldmx4(vh[mt][0], vh[mt][1], vh[mt][2], vh[mt][3],
                  sb + SP_VH + swz((uint32_t)((aRow + mt * 16) * 128 + aColb + kk * 32)));
            ldmx4(vl[mt][0], vl[mt][1], vl[mt][2], vl[mt][3],
                  sb + SP_VL + swz((uint32_t)((aRow + mt * 16) * 128 + aColb + kk * 32)));
        }
        ldmx4(pf[0][0], pf[0][1], pf[1][0], pf[1][1],
              sb + SP_P + swz((uint32_t)(bRow * 128 + bColb + kk * 32)));
#pragma unroll
        for (int mt = 0; mt < 4; mt++)
#pragma unroll
            for (int nt = 0; nt < 2; nt++) {
                mma_h(acc[mt][nt], vh[mt], pf[nt]);
                mma_h(acc[mt][nt], vl[mt], pf[nt]);
            }
    }

    const size_t ob = (size_t)(s * 8 + b) * 4096;
#pragma unroll
    for (int mt = 0; mt < 4; mt++) {
        int t = n0 + wm * 64 + mt * 16 + (lane >> 2);
#pragma unroll
        for (int nt = 0; nt < 2; nt++) {
            int dp = wn * 8 + nt * 4 + (lane & 3);
            uint32_t h0, l0, h1, l1;
            cvt2h(acc[mt][nt][0], acc[mt][nt][1], h0, l0);
            cvt2h(acc[mt][nt][2], acc[mt][nt][3], h1, l1);
            size_t a0 = (ob + t) * 256 + h * 32 + dp;
            g_att_h[a0] = h0; g_att_l[a0] = l0;
            size_t a1 = a0 + 8 * 256;
            g_att_h[a1] = h1; g_att_l[a1] = l1;
        }
    }
}

// ---------------------------------------------------------------------------
// Kernel 3: proj GEMM. grid (cTile 2, nTile 32, sb 16)
// ---------------------------------------------------------------------------
__global__ __launch_bounds__(256, 1) void proj_mma_kernel(
    const float* __restrict__ br, const float* __restrict__ bt,
    float* __restrict__ out)
{
    extern __shared__ char dsm[];
    uint32_t sbr = smem_u32(dsm);
    uint32_t sb = (sbr + 1023) & ~1023u;
    char* ab = dsm + (sb - sbr);

    const int tid = threadIdx.x;
    const int wid = tid >> 5;
    const int lane = tid & 31;
    const int wm = wid & 1, wn = wid >> 1;
    const int z = blockIdx.z;
    const int s = z >> 3, b = z & 7;
    const float* __restrict__ bias = s ? bt : br;
    const int n0 = blockIdx.y * 128;
    const int c0 = blockIdx.x * 256;

    const size_t aBase = (((size_t)(s * 8 + b)) * 4096 + n0) * 256;
    const size_t bBase = ((size_t)s * 512 + c0) * 256;

    float acc[4][8][4];
#pragma unroll
    for (int i = 0; i < 4; i++)
#pragma unroll
        for (int j = 0; j < 8; j++)
#pragma unroll
            for (int r = 0; r < 4; r++) acc[i][j][r] = 0.f;

    fill_big(sb, 0, tid, 0, g_att_h, g_att_l, aBase, g_wp_h, bBase);
    for (int c = 0; c < 8; c++) {
        int st = c & 1;
        if (c < 7) fill_big(sb, st ^ 1, tid, (c + 1) * 32, g_att_h, g_att_l, aBase, g_wp_h, bBase);
        if (c < 7) CP_WAIT1(); else CP_WAIT0();
        __syncthreads();
        mma_big(sb, st, wm, wn, lane, acc);
        __syncthreads();
    }

    // epilogue: [token][channel] + bias via smem transpose (2 passes over wm)
    float* sT = (float*)ab;   // 64 x 264 fp32
    float* outp = out + (size_t)(s * 8 + b) * 2097152;
#pragma unroll
    for (int p = 0; p < 2; p++) {
        if (wm == p) {
#pragma unroll
            for (int mt = 0; mt < 4; mt++)
#pragma unroll
                for (int nj = 0; nj < 8; nj++) {
                    int m = mt * 16 + (lane >> 2);
                    int cc = wn * 64 + nj * 8 + 2 * (lane & 3);
                    sT[m * 264 + cc]           = acc[mt][nj][0];
                    sT[m * 264 + cc + 1]       = acc[mt][nj][1];
                    sT[(m + 8) * 264 + cc]     = acc[mt][nj][2];
                    sT[(m + 8) * 264 + cc + 1] = acc[mt][nj][3];
                }
        }
        __syncthreads();
#pragma unroll
        for (int it = 0; it < 16; it++) {
            int idx = tid + it * 256;
            int row = idx >> 6, ch4 = (idx & 63) * 4;
            int tok = n0 + p * 64 + row;
            float4 vv = *(float4*)&sT[row * 264 + ch4];
            float4 bb = *(const float4*)&bias[c0 + ch4];
            vv.x += bb.x; vv.y += bb.y; vv.z += bb.z; vv.w += bb.w;
            *(float4*)&outp[(size_t)tok * 512 + c0 + ch4] = vv;
        }
        __syncthreads();
    }
}

// ---------------------------------------------------------------------------
extern "C" void kernel_launch(void* const* d_in, const int* in_sizes, int n_in,
                              void* d_out, int out_size)
{
    const float* x        = (const float*)d_in[0];
    const float* x_d      = (const float*)d_in[1];
    const float* W_qkv_r  = (const float*)d_in[2];
    const float* W_qkv_T  = (const float*)d_in[3];
    const float* temp_r   = (const float*)d_in[4];
    const float* temp_T   = (const float*)d_in[5];
    const float* W_proj_r = (const float*)d_in[6];
    const float* b_proj_r = (const float*)d_in[7];
    const float* W_proj_T = (const float*)d_in[8];
    const float* b_proj_T = (const float*)d_in[9];
    float* out = (float*)d_out;

    cudaFuncSetAttribute(qkv_mma_kernel,
        cudaFuncAttributeMaxDynamicSharedMemorySize, QKV_SMEM);
    cudaFuncSetAttribute(proj_mma_kernel,
        cudaFuncAttributeMaxDynamicSharedMemorySize, QKV_SMEM);
    cudaFuncSetAttribute(attn_gram_kernel,
        cudaFuncAttributeMaxDynamicSharedMemorySize, GRAM_SMEM);
    cudaFuncSetAttribute(attn_pv_kernel,
        cudaFuncAttributeMaxDynamicSharedMemorySize, PV_SMEM);

    prep_x_kernel<<<65536, 256>>>(x, x_d);
    prep_w_kernel<<<4096, 256>>>(W_qkv_r, W_qkv_T, W_proj_r, W_proj_T);

    {
        dim3 grid(6, 256, 2);     // c-tile fastest -> A slice L2-reused
        qkv_mma_kernel<<<grid, 256, QKV_SMEM>>>();
    }
    {
        dim3 g1(8, 64, 2);
        attn_gram_kernel<<<g1, 256, GRAM_SMEM>>>();
        attn_softmax_kernel<<<128, 256>>>(temp_r, temp_T);
        dim3 g2(32, 64, 2);
        attn_pv_kernel<<<g2, 256, PV_SMEM>>>();
    }
    {
        dim3 grid(2, 32, 16);     // c-tile fastest
        proj_mma_kernel<<<grid, 256, QKV_SMEM>>>(b_proj_r, b_proj_T, out);
    }
}